// round 15
// baseline (speedup 1.0000x reference)
#include <cuda_runtime.h>
#include <cuda_fp16.h>
#include <math.h>
#include <stdint.h>

// ----------------------------------------------------------------------------
// Problem constants: M=D=10000, FG=FD=256, H1=2, K=64, E=320000
// ----------------------------------------------------------------------------
#define MAXN 10000
#define MAXE 320000
#define CDIM 256

// ------------------------- device scratch (no mallocs) ----------------------
// Tower X
__device__ float  g_bufA[MAXN * 512];
__device__ uint4  g_xsP[650000];
__device__ uint4  g_aggBP[1300000];
__device__ uint4  g_aggCP[650000];
__device__ uint4  g_m1P[650000];
__device__ uint4  g_m2P[330000];
__device__ uint4  g_finP[165000];
__device__ float  g_als[MAXN * 2];
__device__ float  g_ald[MAXN * 2];
__device__ int    g_deg[MAXN + 1];
__device__ int    g_off[MAXN + 1];
__device__ int    g_cur[MAXN];
__device__ int    g_sorted[MAXE];
__device__ uint4  g_pW1[32768];
__device__ uint4  g_pW2[32768];
__device__ uint4  g_pL1[16384];
__device__ uint4  g_pL2[8192];
__device__ uint4  g_pL3[4096];
// Tower Y
__device__ float  g2_bufA[MAXN * 512];
__device__ uint4  g2_xsP[650000];
__device__ uint4  g2_aggBP[1300000];
__device__ uint4  g2_aggCP[650000];
__device__ uint4  g2_m1P[650000];
__device__ uint4  g2_m2P[330000];
__device__ uint4  g2_finP[165000];
__device__ float  g2_als[MAXN * 2];
__device__ float  g2_ald[MAXN * 2];
__device__ int    g2_deg[MAXN + 1];
__device__ int    g2_off[MAXN + 1];
__device__ int    g2_cur[MAXN];
__device__ int    g2_sorted[MAXE];
__device__ uint4  g2_pW1[32768];
__device__ uint4  g2_pW2[32768];
__device__ uint4  g2_pL1[16384];
__device__ uint4  g2_pL2[8192];
__device__ uint4  g2_pL3[4096];

// ------------------------- per-tower arg bundles -----------------------------
struct GemmArgs {
    const uint4* Ap;
    const uint4* Bp;
    const float* bias;
    float* C;
    uint4* Cpack;
};
struct AlArgs {
    const float* xp;
    const float* asrc;
    const float* adst;
    float* als;
    float* ald;
};
struct AggArgs {
    const float* xp;
    const float* als;
    const float* ald;
    const int* src;
    const int* sorted;
    const int* off;
    const float* bias;
    uint4* outP;
};
struct PackXArgs {
    const float* X;
    uint4* out;
};

// ------------------------------ helpers -------------------------------------
__device__ __forceinline__ void split_pair(float a, float b,
                                           uint32_t& hi, uint32_t& lo) {
    __half ha = __float2half_rn(a), hb = __float2half_rn(b);
    float ra = a - __half2float(ha), rb = b - __half2float(hb);
    __half2 h = __halves2half2(ha, hb);
    __half2 l = __floats2half2_rn(ra, rb);
    hi = *(uint32_t*)&h;
    lo = *(uint32_t*)&l;
}

__device__ __forceinline__ void mma_f16(float* c, const uint32_t* a,
                                        const uint32_t* b) {
    asm volatile(
        "mma.sync.aligned.m16n8k16.row.col.f32.f16.f16.f32 "
        "{%0,%1,%2,%3}, {%4,%5,%6,%7}, {%8,%9}, {%0,%1,%2,%3};"
        : "+f"(c[0]), "+f"(c[1]), "+f"(c[2]), "+f"(c[3])
        : "r"(a[0]), "r"(a[1]), "r"(a[2]), "r"(a[3]), "r"(b[0]), "r"(b[1]));
}

__device__ __forceinline__ void cp16(uint32_t dst, const void* src) {
    asm volatile("cp.async.cg.shared.global [%0], [%1], 16;"
                 :: "r"(dst), "l"(src));
}
#define CP_COMMIT() asm volatile("cp.async.commit_group;" ::: "memory")

// ------------------------------ tiny kernels --------------------------------
__global__ void zero_int_kernel(int* p, int n) {
    int i = blockIdx.x * blockDim.x + threadIdx.x;
    if (i < n) p[i] = 0;
}

__global__ void hist_kernel(const int* __restrict__ dst, int E, int* __restrict__ deg) {
    int e = blockIdx.x * blockDim.x + threadIdx.x;
    if (e < E) atomicAdd(&deg[dst[e]], 1);
}

__global__ void scan_kernel(const int* __restrict__ deg, int* __restrict__ off, int n) {
    const int T = 1024;
    int t = threadIdx.x;
    int chunk = (n + T - 1) / T;
    int b = t * chunk;
    int e2 = b + chunk; if (e2 > n) e2 = n;
    int s = 0;
    for (int i = b; i < e2; i++) s += deg[i];
    __shared__ int sh[T];
    sh[t] = s;
    __syncthreads();
    for (int d2 = 1; d2 < T; d2 <<= 1) {
        int v = (t >= d2) ? sh[t - d2] : 0;
        __syncthreads();
        sh[t] += v;
        __syncthreads();
    }
    int run = (t == 0) ? 0 : sh[t - 1];
    for (int i = b; i < e2; i++) { off[i] = run; run += deg[i]; }
    if (t == 0) off[n] = sh[T - 1];
}

__global__ void scatter_kernel(const int* __restrict__ dst, int E,
                               const int* __restrict__ off, int* __restrict__ cur,
                               int* __restrict__ sorted) {
    int e = blockIdx.x * blockDim.x + threadIdx.x;
    if (e < E) {
        int d = dst[e];
        int p = atomicAdd(&cur[d], 1);
        sorted[off[d] + p] = e;
    }
}

// merged pack_x: both towers, tower = idx >= total1
__global__ void pack_x_kernel(PackXArgs a0, PackXArgs a1, int Nrows, int K,
                              int total1, int total) {
    int idx = blockIdx.x * blockDim.x + threadIdx.x;
    if (idx >= total) return;
    const float* X = (idx < total1) ? a0.X : a1.X;
    uint4* out = (idx < total1) ? a0.out : a1.out;
    if (idx >= total1) idx -= total1;
    int KC16 = K >> 4;
    int t = idx / (KC16 * 512);
    int rem = idx - t * (KC16 * 512);
    int c16 = rem >> 9, f = rem & 511;
    int kq = f >> 7, pos = f & 127;
    int r = pos ^ (kq << 1);
    int row = t * 128 + r;
    int k0 = c16 * 16 + kq * 2;
    uint4 v = make_uint4(0u, 0u, 0u, 0u);
    if (row < Nrows) {
        const float* p = &X[(size_t)row * K];
        split_pair(p[k0], p[k0 + 1], v.x, v.z);
        split_pair(p[k0 + 8], p[k0 + 9], v.y, v.w);
    }
    out[idx] = v;
}

__global__ void pack_w_kernel(const float* __restrict__ W, int K, int N,
                              uint4* __restrict__ out, int total) {
    int idx = blockIdx.x * blockDim.x + threadIdx.x;
    if (idx >= total) return;
    int KC16 = K >> 4;
    int t = idx / (KC16 * 512);
    int rem = idx - t * (KC16 * 512);
    int c16 = rem >> 9, f = rem & 511;
    int kq = f >> 7, pos = f & 127;
    int n = t * 128 + (pos ^ (kq << 1));
    int k0 = c16 * 16 + kq * 2;
    uint4 v = make_uint4(0u, 0u, 0u, 0u);
    if (n < N) {
        split_pair(W[(size_t)k0 * N + n], W[(size_t)(k0 + 1) * N + n], v.x, v.z);
        split_pair(W[(size_t)(k0 + 8) * N + n], W[(size_t)(k0 + 9) * N + n], v.y, v.w);
    }
    out[idx] = v;
}

// ------------------------ fp16x3 GEMM via mma.sync --------------------------
// gridDim.z selects tower (identical M,N,K shapes; pointers differ).
#define GEMM_SMEM (3 * 2048 * 16)

template <bool PACK>
__global__ __launch_bounds__(256, 2)
void mma_gemm_kernel(int M, int N, int K, GemmArgs g0, GemmArgs g1,
                     int KCpackTot, int doRelu) {
    extern __shared__ uint4 smem4[];
    const GemmArgs& G = blockIdx.z ? g1 : g0;
    int tid = threadIdx.x, lane = tid & 31, wid = tid >> 5;
    int mBase = blockIdx.y * 128, nBase = blockIdx.x * 128;
    int wm = (wid & 3) * 32, wn = (wid >> 2) * 64;
    int KC16 = K >> 4, KCS = K >> 5;

    float acc[2][8][4];
#pragma unroll
    for (int i = 0; i < 2; i++)
#pragma unroll
        for (int j = 0; j < 8; j++)
#pragma unroll
            for (int l = 0; l < 4; l++) acc[i][j][l] = 0.f;

    const uint4* Asrc = G.Ap + (size_t)blockIdx.y * KC16 * 512;
    const uint4* Bsrc = G.Bp + (size_t)blockIdx.x * KC16 * 512;

    auto do_copy = [&](int chS, int st) {
        uint4* dst = smem4 + st * 2048;
        uint32_t dA = (uint32_t)__cvta_generic_to_shared(dst + tid);
        const uint4* sA = Asrc + chS * 1024 + tid;
#pragma unroll
        for (int i = 0; i < 4; i++)
            cp16(dA + i * 256 * 16, sA + i * 256);
        uint32_t dB = (uint32_t)__cvta_generic_to_shared(dst + 1024 + tid);
        const uint4* sB = Bsrc + chS * 1024 + tid;
#pragma unroll
        for (int i = 0; i < 4; i++)
            cp16(dB + i * 256 * 16, sB + i * 256);
    };

    do_copy(0, 0); CP_COMMIT();
    if (1 < KCS) { do_copy(1, 1); }
    CP_COMMIT();

    int kq = lane & 3, sx = kq << 1;
    int rquad = lane >> 2;

    for (int ch = 0; ch < KCS; ch++) {
        if (ch >= KCS - 2)
            asm volatile("cp.async.wait_group 0;" ::: "memory");
        else
            asm volatile("cp.async.wait_group 1;" ::: "memory");
        __syncthreads();

        const uint4* As = smem4 + (ch % 3) * 2048;
        const uint4* Bs = As + 1024;

#pragma unroll
        for (int c2 = 0; c2 < 2; c2++) {
            int base = c2 * 512 + kq * 128;
            uint32_t ah[2][4], al[2][4];
#pragma unroll
            for (int mt = 0; mt < 2; mt++) {
                int rr = wm + rquad + mt * 16;
                uint4 v0 = As[base + (rr ^ sx)];
                uint4 v1 = As[base + ((rr + 8) ^ sx)];
                ah[mt][0] = v0.x; ah[mt][1] = v1.x;
                ah[mt][2] = v0.y; ah[mt][3] = v1.y;
                al[mt][0] = v0.z; al[mt][1] = v1.z;
                al[mt][2] = v0.w; al[mt][3] = v1.w;
            }
            uint32_t bh[8][2], bl[8][2];
#pragma unroll
            for (int j = 0; j < 8; j++) {
                int bn = wn + j * 8 + rquad;
                uint4 g = Bs[base + (bn ^ sx)];
                bh[j][0] = g.x; bh[j][1] = g.y;
                bl[j][0] = g.z; bl[j][1] = g.w;
            }
#pragma unroll
            for (int j = 0; j < 8; j++)
#pragma unroll
                for (int mt = 0; mt < 2; mt++)
                    mma_f16(acc[mt][j], ah[mt], bh[j]);
#pragma unroll
            for (int j = 0; j < 8; j++)
#pragma unroll
                for (int mt = 0; mt < 2; mt++)
                    mma_f16(acc[mt][j], al[mt], bh[j]);
#pragma unroll
            for (int j = 0; j < 8; j++)
#pragma unroll
                for (int mt = 0; mt < 2; mt++)
                    mma_f16(acc[mt][j], ah[mt], bl[j]);
        }

        if (ch + 2 < KCS) do_copy(ch + 2, (ch + 2) % 3);
        CP_COMMIT();
    }

    // ------------------------------ epilogue --------------------------------
#pragma unroll
    for (int mt = 0; mt < 2; mt++) {
        int r0loc = wm + mt * 16 + rquad;
        int gr0 = mBase + r0loc, gr1 = gr0 + 8;
        if (!PACK) {
#pragma unroll
            for (int nt = 0; nt < 8; nt++) {
                int c = nBase + wn + nt * 8 + kq * 2;
                if (c >= N) continue;
                float b0 = G.bias ? G.bias[c] : 0.f;
                float b1 = G.bias ? G.bias[c + 1] : 0.f;
                if (gr0 < M) {
                    float v0 = acc[mt][nt][0] + b0, v1 = acc[mt][nt][1] + b1;
                    if (doRelu) { v0 = fmaxf(v0, 0.f); v1 = fmaxf(v1, 0.f); }
                    *(float2*)&G.C[(size_t)gr0 * N + c] = make_float2(v0, v1);
                }
                if (gr1 < M) {
                    float v2 = acc[mt][nt][2] + b0, v3 = acc[mt][nt][3] + b1;
                    if (doRelu) { v2 = fmaxf(v2, 0.f); v3 = fmaxf(v3, 0.f); }
                    *(float2*)&G.C[(size_t)gr1 * N + c] = make_float2(v2, v3);
                }
            }
        } else {
#pragma unroll
            for (int ntp = 0; ntp < 8; ntp += 2) {
                int ncol = nBase + wn + ntp * 8 + kq * 2;
                int c16 = ncol >> 4;
                if (c16 >= KCpackTot) continue;
                float b0 = G.bias ? G.bias[ncol] : 0.f;
                float b1 = G.bias ? G.bias[ncol + 1] : 0.f;
                float b8 = G.bias ? G.bias[ncol + 8] : 0.f;
                float b9 = G.bias ? G.bias[ncol + 9] : 0.f;
                size_t dbase = ((size_t)blockIdx.y * KCpackTot + c16) * 512 +
                               kq * 128;
#pragma unroll
                for (int hlf = 0; hlf < 2; hlf++) {
                    int rloc = r0loc + hlf * 8;
                    int grow = mBase + rloc;
                    uint4 v = make_uint4(0u, 0u, 0u, 0u);
                    if (grow < M) {
                        float p0 = acc[mt][ntp][hlf * 2 + 0] + b0;
                        float p1 = acc[mt][ntp][hlf * 2 + 1] + b1;
                        float q0 = acc[mt][ntp + 1][hlf * 2 + 0] + b8;
                        float q1 = acc[mt][ntp + 1][hlf * 2 + 1] + b9;
                        if (doRelu) {
                            p0 = fmaxf(p0, 0.f); p1 = fmaxf(p1, 0.f);
                            q0 = fmaxf(q0, 0.f); q1 = fmaxf(q1, 0.f);
                        }
                        split_pair(p0, p1, v.x, v.z);
                        split_pair(q0, q1, v.y, v.w);
                    }
                    G.Cpack[dbase + (rloc ^ sx)] = v;
                }
            }
        }
    }
}

// --------------------------- GAT-specific kernels ---------------------------
// merged warp-per-node attention logits: warps [0,N) tower0, [N,2N) tower1
__global__ void compute_al(AlArgs a0, AlArgs a1, int H, int N) {
    int warp = (blockIdx.x * blockDim.x + threadIdx.x) >> 5;
    int lane = threadIdx.x & 31;
    if (warp >= 2 * N) return;
    const AlArgs& A = (warp < N) ? a0 : a1;
    if (warp >= N) warp -= N;
    int HC = H * CDIM;
    for (int h = 0; h < H; h++) {
        const float4* xr = (const float4*)(A.xp + (size_t)warp * HC + h * CDIM);
        const float4* ar = (const float4*)(A.asrc + h * CDIM);
        const float4* dr = (const float4*)(A.adst + h * CDIM);
        float s1 = 0.f, s2 = 0.f;
#pragma unroll
        for (int i = 0; i < 2; i++) {
            float4 x = xr[lane * 2 + i];
            float4 a = ar[lane * 2 + i];
            float4 dd = dr[lane * 2 + i];
            s1 += x.x * a.x + x.y * a.y + x.z * a.z + x.w * a.w;
            s2 += x.x * dd.x + x.y * dd.y + x.z * dd.z + x.w * dd.w;
        }
#pragma unroll
        for (int o = 16; o > 0; o >>= 1) {
            s1 += __shfl_down_sync(0xffffffffu, s1, o);
            s2 += __shfl_down_sync(0xffffffffu, s2, o);
        }
        if (lane == 0) { A.als[warp * H + h] = s1; A.ald[warp * H + h] = s2; }
    }
}

// merged fused logits + softmax + gather-aggregate; blocks [0,N) t0, [N,2N) t1
__global__ void gat_aggregate(AggArgs a0, AggArgs a1, int H, int N) {
    int d = blockIdx.x, tid = threadIdx.x;
    const AggArgs& A = (d < N) ? a0 : a1;
    if (d >= N) d -= N;
    const float* xp = A.xp;
    const float* als = A.als;
    const float* ald = A.ald;
    const int* src = A.src;
    const int* sorted = A.sorted;
    const float* bias = A.bias;
    int beg = A.off[d];
    int deg = A.off[d + 1] - beg;
    int HC = H * CDIM;
    __shared__ float sh[16];
    __shared__ float s_b[2];
    __shared__ float s_alpha[512];
    __shared__ int   s_row[256];
    __shared__ float s_out[512];

    if (H == 2 && deg <= 256) {
        int srow = 0;
        float lg0 = -1e30f, lg1 = -1e30f;
        float ald0 = ald[d * 2], ald1 = ald[d * 2 + 1];
        if (tid < deg) {
            srow = src[sorted[beg + tid]];
            s_row[tid] = srow;
            float v0 = als[srow * 2] + ald0;
            float v1 = als[srow * 2 + 1] + ald1;
            lg0 = v0 > 0.f ? v0 : 0.2f * v0;
            lg1 = v1 > 0.f ? v1 : 0.2f * v1;
        }
        float m0 = lg0, m1 = lg1;
#pragma unroll
        for (int o = 16; o > 0; o >>= 1) {
            m0 = fmaxf(m0, __shfl_down_sync(0xffffffffu, m0, o));
            m1 = fmaxf(m1, __shfl_down_sync(0xffffffffu, m1, o));
        }
        if ((tid & 31) == 0) { sh[tid >> 5] = m0; sh[8 + (tid >> 5)] = m1; }
        __syncthreads();
        if (tid < 8) {
            m0 = sh[tid]; m1 = sh[8 + tid];
#pragma unroll
            for (int o = 4; o > 0; o >>= 1) {
                m0 = fmaxf(m0, __shfl_down_sync(0xffu, m0, o));
                m1 = fmaxf(m1, __shfl_down_sync(0xffu, m1, o));
            }
            if (tid == 0) { s_b[0] = m0; s_b[1] = m1; }
        }
        __syncthreads();
        float g0 = s_b[0], g1 = s_b[1];

        float e0 = (tid < deg) ? __expf(lg0 - g0) : 0.f;
        float e1 = (tid < deg) ? __expf(lg1 - g1) : 0.f;
        s_alpha[tid] = e0;
        s_alpha[256 + tid] = e1;
        float t0 = e0, t1 = e1;
#pragma unroll
        for (int o = 16; o > 0; o >>= 1) {
            t0 += __shfl_down_sync(0xffffffffu, t0, o);
            t1 += __shfl_down_sync(0xffffffffu, t1, o);
        }
        if ((tid & 31) == 0) { sh[tid >> 5] = t0; sh[8 + (tid >> 5)] = t1; }
        __syncthreads();
        if (tid < 8) {
            t0 = sh[tid]; t1 = sh[8 + tid];
#pragma unroll
            for (int o = 4; o > 0; o >>= 1) {
                t0 += __shfl_down_sync(0xffu, t0, o);
                t1 += __shfl_down_sync(0xffu, t1, o);
            }
            if (tid == 0) { s_b[0] = t0; s_b[1] = t1; }
        }
        __syncthreads();
        float inv0 = 1.f / (s_b[0] + 1e-16f);
        float inv1 = 1.f / (s_b[1] + 1e-16f);

        const float* xb = xp + tid;
        float a0v = 0.f, a1v = 0.f, c0 = 0.f, c1 = 0.f;
        int j = 0;
        for (; j + 2 <= deg; j += 2) {
            size_t r0 = (size_t)s_row[j] * 512;
            size_t r1 = (size_t)s_row[j + 1] * 512;
            a0v += s_alpha[j] * xb[r0];
            c0 += s_alpha[256 + j] * xb[r0 + 256];
            a1v += s_alpha[j + 1] * xb[r1];
            c1 += s_alpha[256 + j + 1] * xb[r1 + 256];
        }
        if (j < deg) {
            size_t r0 = (size_t)s_row[j] * 512;
            a0v += s_alpha[j] * xb[r0];
            c0 += s_alpha[256 + j] * xb[r0 + 256];
        }
        s_out[tid] = fmaxf((a0v + a1v) * inv0 + bias[tid], 0.f);
        s_out[256 + tid] = fmaxf((c0 + c1) * inv1 + bias[256 + tid], 0.f);
    } else if (deg <= 256) {
        int srow = 0;
        if (tid < deg) {
            srow = src[sorted[beg + tid]];
            s_row[tid] = srow;
        }
        for (int h = 0; h < H; h++) {
            float aldd = ald[d * H + h];
            float lg = -1e30f;
            if (tid < deg) {
                float v = als[srow * H + h] + aldd;
                lg = v > 0.f ? v : 0.2f * v;
            }
            float mx = lg;
#pragma unroll
            for (int o = 16; o > 0; o >>= 1)
                mx = fmaxf(mx, __shfl_down_sync(0xffffffffu, mx, o));
            if ((tid & 31) == 0) sh[tid >> 5] = mx;
            __syncthreads();
            if (tid < 8) {
                mx = sh[tid];
#pragma unroll
                for (int o = 4; o > 0; o >>= 1)
                    mx = fmaxf(mx, __shfl_down_sync(0xffu, mx, o));
                if (tid == 0) s_b[0] = mx;
            }
            __syncthreads();
            float gmax = s_b[0];

            float ee = (tid < deg) ? __expf(lg - gmax) : 0.f;
            s_alpha[tid] = ee;
            float sm = ee;
#pragma unroll
            for (int o = 16; o > 0; o >>= 1) sm += __shfl_down_sync(0xffffffffu, sm, o);
            if ((tid & 31) == 0) sh[tid >> 5] = sm;
            __syncthreads();
            if (tid < 8) {
                sm = sh[tid];
#pragma unroll
                for (int o = 4; o > 0; o >>= 1) sm += __shfl_down_sync(0xffu, sm, o);
                if (tid == 0) s_b[0] = sm;
            }
            __syncthreads();
            float inv = 1.f / (s_b[0] + 1e-16f);

            const float* xph = xp + h * CDIM + tid;
            float a0v = 0.f, a1v = 0.f, a2 = 0.f, a3 = 0.f;
            int j = 0;
            for (; j + 4 <= deg; j += 4) {
                a0v += s_alpha[j + 0] * xph[(size_t)s_row[j + 0] * HC];
                a1v += s_alpha[j + 1] * xph[(size_t)s_row[j + 1] * HC];
                a2 += s_alpha[j + 2] * xph[(size_t)s_row[j + 2] * HC];
                a3 += s_alpha[j + 3] * xph[(size_t)s_row[j + 3] * HC];
            }
            for (; j < deg; j++)
                a0v += s_alpha[j] * xph[(size_t)s_row[j] * HC];
            s_out[h * CDIM + tid] =
                fmaxf(((a0v + a1v) + (a2 + a3)) * inv + bias[h * CDIM + tid], 0.f);
            __syncthreads();
        }
    } else {
        for (int h = 0; h < H; h++) {
            float aldd = ald[d * H + h];
            float mx = -1e30f;
            for (int i = tid; i < deg; i += 256) {
                int s = src[sorted[beg + i]];
                float v = als[s * H + h] + aldd;
                v = v > 0.f ? v : 0.2f * v;
                mx = fmaxf(mx, v);
            }
#pragma unroll
            for (int o = 16; o > 0; o >>= 1)
                mx = fmaxf(mx, __shfl_down_sync(0xffffffffu, mx, o));
            if ((tid & 31) == 0) sh[tid >> 5] = mx;
            __syncthreads();
            if (tid < 8) {
                mx = sh[tid];
#pragma unroll
                for (int o = 4; o > 0; o >>= 1)
                    mx = fmaxf(mx, __shfl_down_sync(0xffu, mx, o));
                if (tid == 0) s_b[0] = mx;
            }
            __syncthreads();
            float gmax = s_b[0];

            float sm = 0.f;
            for (int i = tid; i < deg; i += 256) {
                int s = src[sorted[beg + i]];
                float v = als[s * H + h] + aldd;
                v = v > 0.f ? v : 0.2f * v;
                sm += __expf(v - gmax);
            }
#pragma unroll
            for (int o = 16; o > 0; o >>= 1) sm += __shfl_down_sync(0xffffffffu, sm, o);
            if ((tid & 31) == 0) sh[tid >> 5] = sm;
            __syncthreads();
            if (tid < 8) {
                sm = sh[tid];
#pragma unroll
                for (int o = 4; o > 0; o >>= 1) sm += __shfl_down_sync(0xffu, sm, o);
                if (tid == 0) s_b[0] = sm;
            }
            __syncthreads();
            float inv = 1.f / (s_b[0] + 1e-16f);

            float acc = 0.f;
            for (int base = 0; base < deg; base += 256) {
                __syncthreads();
                int i = base + tid;
                if (i < deg) {
                    int s = src[sorted[beg + i]];
                    float v = als[s * H + h] + aldd;
                    v = v > 0.f ? v : 0.2f * v;
                    s_alpha[tid] = __expf(v - gmax) * inv;
                    s_row[tid]   = s;
                }
                __syncthreads();
                int lim = deg - base; if (lim > 256) lim = 256;
                for (int j = 0; j < lim; j++) {
                    acc += s_alpha[j] * xp[(size_t)s_row[j] * HC + h * CDIM + tid];
                }
            }
            s_out[h * CDIM + tid] = fmaxf(acc + bias[h * CDIM + tid], 0.f);
            __syncthreads();
        }
    }

    __syncthreads();
    int HC4 = HC >> 2;
    if (tid < HC4) {
        int c16 = tid >> 2, kq = tid & 3;
        int k0 = c16 * 16 + kq * 2;
        uint4 v;
        split_pair(s_out[k0], s_out[k0 + 1], v.x, v.z);
        split_pair(s_out[k0 + 8], s_out[k0 + 9], v.y, v.w);
        int t = d >> 7, dloc = d & 127;
        A.outP[((size_t)t * (HC >> 4) + c16) * 512 + kq * 128 + (dloc ^ (kq << 1))] = v;
    }
}

// --------------------------------- host -------------------------------------
static void run_gemm2_f(cudaStream_t st, GemmArgs g0, GemmArgs g1,
                        int M, int N, int K, bool relu, int nz) {
    dim3 grid((N + 127) / 128, (M + 127) / 128, nz);
    mma_gemm_kernel<false><<<grid, 256, GEMM_SMEM, st>>>(M, N, K, g0, g1, 0,
                                                         relu ? 1 : 0);
}

static void run_gemm2_p(cudaStream_t st, GemmArgs g0, GemmArgs g1,
                        int KCpackTot, int M, int N, int K, bool relu) {
    dim3 grid((N + 127) / 128, (M + 127) / 128, 2);
    mma_gemm_kernel<true><<<grid, 256, GEMM_SMEM, st>>>(M, N, K, g0, g1,
                                                        KCpackTot, relu ? 1 : 0);
}

static void run_pack_w(cudaStream_t st, const float* W, int K, int N, uint4* out) {
    int total = ((N + 127) / 128) * (K >> 4) * 512;
    pack_w_kernel<<<(total + 255) / 256, 256, 0, st>>>(W, K, N, out, total);
}

struct Tower {
    float *bufA;
    uint4 *xsP, *aggBP, *aggCP, *m1P, *m2P, *finP;
    float *als, *ald;
    int *deg, *off, *cur, *sorted;
    uint4 *pW1, *pW2, *pL1, *pL2, *pL3;
};

#define GSA(p, s) cudaGetSymbolAddress((void**)&(p), s)

extern "C" void kernel_launch(void* const* d_in, const int* in_sizes, int n_in,
                              void* d_out, int out_size) {
    const float* x_m  = (const float*)d_in[0];
    const float* x_d  = (const float*)d_in[1];
    const int*   eix  = (const int*)d_in[2];
    const int*   eiy  = (const int*)d_in[3];
    const float* Wx1 = (const float*)d_in[4];
    const float* ax1s = (const float*)d_in[5];
    const float* ax1d = (const float*)d_in[6];
    const float* bx1 = (const float*)d_in[7];
    const float* Wx2 = (const float*)d_in[8];
    const float* ax2s = (const float*)d_in[9];
    const float* ax2d = (const float*)d_in[10];
    const float* bx2 = (const float*)d_in[11];
    const float* Wy1 = (const float*)d_in[12];
    const float* ay1s = (const float*)d_in[13];
    const float* ay1d = (const float*)d_in[14];
    const float* by1 = (const float*)d_in[15];
    const float* Wy2 = (const float*)d_in[16];
    const float* ay2s = (const float*)d_in[17];
    const float* ay2d = (const float*)d_in[18];
    const float* by2 = (const float*)d_in[19];
    const float* lwx1 = (const float*)d_in[20];
    const float* lbx1 = (const float*)d_in[21];
    const float* lwx2 = (const float*)d_in[22];
    const float* lbx2 = (const float*)d_in[23];
    const float* lwx3 = (const float*)d_in[24];
    const float* lbx3 = (const float*)d_in[25];
    const float* lwy1 = (const float*)d_in[26];
    const float* lby1 = (const float*)d_in[27];
    const float* lwy2 = (const float*)d_in[28];
    const float* lby2 = (const float*)d_in[29];
    const float* lwy3 = (const float*)d_in[30];
    const float* lby3 = (const float*)d_in[31];

    int M  = in_sizes[0] / 256;   // == D for this instance
    int D  = in_sizes[1] / 256;
    int EX = in_sizes[2] / 2;
    int EY = in_sizes[3] / 2;
    const int* srcX = eix; const int* dstX = eix + EX;
    const int* srcY = eiy; const int* dstY = eiy + EY;

    static bool s_init = false;
    static cudaStream_t sS;
    static cudaEvent_t evRoot, evW1, evSort, evPk;
    if (!s_init) {
        cudaStreamCreateWithFlags(&sS, cudaStreamNonBlocking);
        cudaEventCreateWithFlags(&evRoot, cudaEventDisableTiming);
        cudaEventCreateWithFlags(&evW1, cudaEventDisableTiming);
        cudaEventCreateWithFlags(&evSort, cudaEventDisableTiming);
        cudaEventCreateWithFlags(&evPk, cudaEventDisableTiming);
        cudaFuncSetAttribute(mma_gemm_kernel<false>,
                             cudaFuncAttributeMaxDynamicSharedMemorySize, GEMM_SMEM);
        cudaFuncSetAttribute(mma_gemm_kernel<true>,
                             cudaFuncAttributeMaxDynamicSharedMemorySize, GEMM_SMEM);
        s_init = true;
    }

    Tower TX, TY;
    GSA(TX.bufA, g_bufA);
    GSA(TX.xsP, g_xsP); GSA(TX.aggBP, g_aggBP);
    GSA(TX.aggCP, g_aggCP); GSA(TX.m1P, g_m1P); GSA(TX.m2P, g_m2P);
    GSA(TX.finP, g_finP);
    GSA(TX.als, g_als); GSA(TX.ald, g_ald);
    GSA(TX.deg, g_deg); GSA(TX.off, g_off); GSA(TX.cur, g_cur);
    GSA(TX.sorted, g_sorted);
    GSA(TX.pW1, g_pW1); GSA(TX.pW2, g_pW2);
    GSA(TX.pL1, g_pL1); GSA(TX.pL2, g_pL2); GSA(TX.pL3, g_pL3);

    GSA(TY.bufA, g2_bufA);
    GSA(TY.xsP, g2_xsP); GSA(TY.aggBP, g2_aggBP);
    GSA(TY.aggCP, g2_aggCP); GSA(TY.m1P, g2_m1P); GSA(TY.m2P, g2_m2P);
    GSA(TY.finP, g2_finP);
    GSA(TY.als, g2_als); GSA(TY.ald, g2_ald);
    GSA(TY.deg, g2_deg); GSA(TY.off, g2_off); GSA(TY.cur, g2_cur);
    GSA(TY.sorted, g2_sorted);
    GSA(TY.pW1, g2_pW1); GSA(TY.pW2, g2_pW2);
    GSA(TY.pL1, g2_pL1); GSA(TY.pL2, g2_pL2); GSA(TY.pL3, g2_pL3);

    cudaEventRecord(evRoot, 0);
    cudaStreamWaitEvent(sS, evRoot, 0);

    // ---- fork stream: W1 packs, sorts, remaining packs (off critical path) --
    run_pack_w(sS, Wx1, 256, 512, TX.pW1);
    run_pack_w(sS, Wy1, 256, 512, TY.pW1);
    cudaEventRecord(evW1, sS);
    zero_int_kernel<<<(M + 256) / 256, 256, 0, sS>>>(TX.deg, M + 1);
    zero_int_kernel<<<(M + 255) / 256, 256, 0, sS>>>(TX.cur, M);
    zero_int_kernel<<<(D + 256) / 256, 256, 0, sS>>>(TY.deg, D + 1);
    zero_int_kernel<<<(D + 255) / 256, 256, 0, sS>>>(TY.cur, D);
    hist_kernel<<<(EX + 255) / 256, 256, 0, sS>>>(dstX, EX, TX.deg);
    hist_kernel<<<(EY + 255) / 256, 256, 0, sS>>>(dstY, EY, TY.deg);
    scan_kernel<<<1, 1024, 0, sS>>>(TX.deg, TX.off, M);
    scan_kernel<<<1, 1024, 0, sS>>>(TY.deg, TY.off, D);
    scatter_kernel<<<(EX + 255) / 256, 256, 0, sS>>>(dstX, EX, TX.off, TX.cur,
                                                     TX.sorted);
    scatter_kernel<<<(EY + 255) / 256, 256, 0, sS>>>(dstY, EY, TY.off, TY.cur,
                                                     TY.sorted);
    cudaEventRecord(evSort, sS);
    run_pack_w(sS, Wx2, 512, 256, TX.pW2);
    run_pack_w(sS, Wy2, 512, 256, TY.pW2);
    run_pack_w(sS, lwx1, 256, 256, TX.pL1);
    run_pack_w(sS, lwy1, 256, 256, TY.pL1);
    run_pack_w(sS, lwx2, 256, 128, TX.pL2);
    run_pack_w(sS, lwy2, 256, 128, TY.pL2);
    run_pack_w(sS, lwx3, 128, 64, TX.pL3);
    run_pack_w(sS, lwy3, 128, 64, TY.pL3);
    cudaEventRecord(evPk, sS);

    // ---- main stream: merged both-tower launches ----------------------------
    int NT = (M + 127) / 128;
    int xTotal1 = NT * 16 * 512;
    pack_x_kernel<<<(2 * xTotal1 + 255) / 256, 256>>>(
        PackXArgs{x_m, TX.xsP}, PackXArgs{x_d, TY.xsP}, M, 256, xTotal1,
        2 * xTotal1);

    cudaStreamWaitEvent(0, evW1, 0);
    run_gemm2_f(0, GemmArgs{TX.xsP, TX.pW1, nullptr, TX.bufA, nullptr},
                GemmArgs{TY.xsP, TY.pW1, nullptr, TY.bufA, nullptr},
                M, 512, 256, false, 2);

    int alGrid = (2 * M * 32 + 255) / 256;
    compute_al<<<alGrid, 256>>>(AlArgs{TX.bufA, ax1s, ax1d, TX.als, TX.ald},
                                AlArgs{TY.bufA, ay1s, ay1d, TY.als, TY.ald}, 2, M);
    cudaStreamWaitEvent(0, evSort, 0);
    gat_aggregate<<<2 * M, 256>>>(
        AggArgs{TX.bufA, TX.als, TX.ald, srcX, TX.sorted, TX.off, bx1, TX.aggBP},
        AggArgs{TY.bufA, TY.als, TY.ald, srcY, TY.sorted, TY.off, by1, TY.aggBP},
        2, M);

    cudaStreamWaitEvent(0, evPk, 0);
    run_gemm2_f(0, GemmArgs{TX.aggBP, TX.pW2, nullptr, TX.bufA, nullptr},
                GemmArgs{TY.aggBP, TY.pW2, nullptr, TY.bufA, nullptr},
                M, 256, 512, false, 2);
    compute_al<<<alGrid, 256>>>(AlArgs{TX.bufA, ax2s, ax2d, TX.als, TX.ald},
                                AlArgs{TY.bufA, ay2s, ay2d, TY.als, TY.ald}, 1, M);
    gat_aggregate<<<2 * M, 256>>>(
        AggArgs{TX.bufA, TX.als, TX.ald, srcX, TX.sorted, TX.off, bx2, TX.aggCP},
        AggArgs{TY.bufA, TY.als, TY.ald, srcY, TY.sorted, TY.off, by2, TY.aggCP},
        1, M);

    run_gemm2_p(0, GemmArgs{TX.aggCP, TX.pL1, lbx1, nullptr, TX.m1P},
                GemmArgs{TY.aggCP, TY.pL1, lby1, nullptr, TY.m1P},
                16, M, 256, 256, true);
    run_gemm2_p(0, GemmArgs{TX.m1P, TX.pL2, lbx2, nullptr, TX.m2P},
                GemmArgs{TY.m1P, TY.pL2, lby2, nullptr, TY.m2P},
                8, M, 128, 256, true);
    run_gemm2_p(0, GemmArgs{TX.m2P, TX.pL3, lbx3, nullptr, TX.finP},
                GemmArgs{TY.m2P, TY.pL3, lby3, nullptr, TY.finP},
                4, M, 64, 128, true);

    // final: out = finX @ finY^T
    GemmArgs gf{TX.finP, TY.finP, nullptr, (float*)d_out, nullptr};
    run_gemm2_f(0, gf, gf, M, D, 64, false, 1);
}

// round 16
// speedup vs baseline: 1.1080x; 1.1080x over previous
#include <cuda_runtime.h>
#include <cuda_fp16.h>
#include <math.h>
#include <stdint.h>

// ----------------------------------------------------------------------------
// Problem constants: M=D=10000, FG=FD=256, H1=2, K=64, E=320000
// ----------------------------------------------------------------------------
#define MAXN 10000
#define MAXE 320000
#define CDIM 256

// ------------------------- device scratch (no mallocs) ----------------------
// Tower X
__device__ float  g_bufA[MAXN * 512];
__device__ uint4  g_xsP[650000];
__device__ uint4  g_aggBP[1300000];
__device__ uint4  g_aggCP[650000];
__device__ uint4  g_m1P[650000];
__device__ uint4  g_m2P[330000];
__device__ uint4  g_finP[165000];
__device__ float  g_als[MAXN * 2];
__device__ float  g_ald[MAXN * 2];
__device__ int    g_deg[MAXN + 1];
__device__ int    g_off[MAXN + 1];
__device__ int    g_cur[MAXN];
__device__ int    g_sorted[MAXE];
__device__ uint4  g_pW1[32768];
__device__ uint4  g_pW2[32768];
__device__ uint4  g_pL1[16384];
__device__ uint4  g_pL2[8192];
__device__ uint4  g_pL3[4096];
// Tower Y
__device__ float  g2_bufA[MAXN * 512];
__device__ uint4  g2_xsP[650000];
__device__ uint4  g2_aggBP[1300000];
__device__ uint4  g2_aggCP[650000];
__device__ uint4  g2_m1P[650000];
__device__ uint4  g2_m2P[330000];
__device__ uint4  g2_finP[165000];
__device__ float  g2_als[MAXN * 2];
__device__ float  g2_ald[MAXN * 2];
__device__ int    g2_deg[MAXN + 1];
__device__ int    g2_off[MAXN + 1];
__device__ int    g2_cur[MAXN];
__device__ int    g2_sorted[MAXE];
__device__ uint4  g2_pW1[32768];
__device__ uint4  g2_pW2[32768];
__device__ uint4  g2_pL1[16384];
__device__ uint4  g2_pL2[8192];
__device__ uint4  g2_pL3[4096];

// ------------------------------ helpers -------------------------------------
__device__ __forceinline__ void split_pair(float a, float b,
                                           uint32_t& hi, uint32_t& lo) {
    __half ha = __float2half_rn(a), hb = __float2half_rn(b);
    float ra = a - __half2float(ha), rb = b - __half2float(hb);
    __half2 h = __halves2half2(ha, hb);
    __half2 l = __floats2half2_rn(ra, rb);
    hi = *(uint32_t*)&h;
    lo = *(uint32_t*)&l;
}

__device__ __forceinline__ void mma_f16(float* c, const uint32_t* a,
                                        const uint32_t* b) {
    asm volatile(
        "mma.sync.aligned.m16n8k16.row.col.f32.f16.f16.f32 "
        "{%0,%1,%2,%3}, {%4,%5,%6,%7}, {%8,%9}, {%0,%1,%2,%3};"
        : "+f"(c[0]), "+f"(c[1]), "+f"(c[2]), "+f"(c[3])
        : "r"(a[0]), "r"(a[1]), "r"(a[2]), "r"(a[3]), "r"(b[0]), "r"(b[1]));
}

__device__ __forceinline__ void cp16(uint32_t dst, const void* src) {
    asm volatile("cp.async.cg.shared.global [%0], [%1], 16;"
                 :: "r"(dst), "l"(src));
}
#define CP_COMMIT() asm volatile("cp.async.commit_group;" ::: "memory")

// ------------------------------ tiny kernels --------------------------------
__global__ void zero_int_kernel(int* p, int n) {
    int i = blockIdx.x * blockDim.x + threadIdx.x;
    if (i < n) p[i] = 0;
}

__global__ void hist_kernel(const int* __restrict__ dst, int E, int* __restrict__ deg) {
    int e = blockIdx.x * blockDim.x + threadIdx.x;
    if (e < E) atomicAdd(&deg[dst[e]], 1);
}

__global__ void scan_kernel(const int* __restrict__ deg, int* __restrict__ off, int n) {
    const int T = 1024;
    int t = threadIdx.x;
    int chunk = (n + T - 1) / T;
    int b = t * chunk;
    int e2 = b + chunk; if (e2 > n) e2 = n;
    int s = 0;
    for (int i = b; i < e2; i++) s += deg[i];
    __shared__ int sh[T];
    sh[t] = s;
    __syncthreads();
    for (int d2 = 1; d2 < T; d2 <<= 1) {
        int v = (t >= d2) ? sh[t - d2] : 0;
        __syncthreads();
        sh[t] += v;
        __syncthreads();
    }
    int run = (t == 0) ? 0 : sh[t - 1];
    for (int i = b; i < e2; i++) { off[i] = run; run += deg[i]; }
    if (t == 0) off[n] = sh[T - 1];
}

__global__ void scatter_kernel(const int* __restrict__ dst, int E,
                               const int* __restrict__ off, int* __restrict__ cur,
                               int* __restrict__ sorted) {
    int e = blockIdx.x * blockDim.x + threadIdx.x;
    if (e < E) {
        int d = dst[e];
        int p = atomicAdd(&cur[d], 1);
        sorted[off[d] + p] = e;
    }
}

__global__ void pack_x_kernel(const float* __restrict__ X, int Nrows, int K,
                              uint4* __restrict__ out, int total) {
    int idx = blockIdx.x * blockDim.x + threadIdx.x;
    if (idx >= total) return;
    int KC16 = K >> 4;
    int t = idx / (KC16 * 512);
    int rem = idx - t * (KC16 * 512);
    int c16 = rem >> 9, f = rem & 511;
    int kq = f >> 7, pos = f & 127;
    int r = pos ^ (kq << 1);
    int row = t * 128 + r;
    int k0 = c16 * 16 + kq * 2;
    uint4 v = make_uint4(0u, 0u, 0u, 0u);
    if (row < Nrows) {
        const float* p = &X[(size_t)row * K];
        split_pair(p[k0], p[k0 + 1], v.x, v.z);
        split_pair(p[k0 + 8], p[k0 + 9], v.y, v.w);
    }
    out[idx] = v;
}

__global__ void pack_w_kernel(const float* __restrict__ W, int K, int N,
                              uint4* __restrict__ out, int total) {
    int idx = blockIdx.x * blockDim.x + threadIdx.x;
    if (idx >= total) return;
    int KC16 = K >> 4;
    int t = idx / (KC16 * 512);
    int rem = idx - t * (KC16 * 512);
    int c16 = rem >> 9, f = rem & 511;
    int kq = f >> 7, pos = f & 127;
    int n = t * 128 + (pos ^ (kq << 1));
    int k0 = c16 * 16 + kq * 2;
    uint4 v = make_uint4(0u, 0u, 0u, 0u);
    if (n < N) {
        split_pair(W[(size_t)k0 * N + n], W[(size_t)(k0 + 1) * N + n], v.x, v.z);
        split_pair(W[(size_t)(k0 + 8) * N + n], W[(size_t)(k0 + 9) * N + n], v.y, v.w);
    }
    out[idx] = v;
}

// ------------------------ fp16x3 GEMM via mma.sync --------------------------
#define GEMM_SMEM (3 * 2048 * 16)

template <bool PACK>
__global__ __launch_bounds__(256, 2)
void mma_gemm_kernel(int M, int N, int K,
                     const uint4* __restrict__ Ap, const uint4* __restrict__ Bp,
                     const float* __restrict__ bias,
                     float* __restrict__ C,
                     uint4* __restrict__ Cpack, int KCpackTot,
                     int doRelu) {
    extern __shared__ uint4 smem4[];
    int tid = threadIdx.x, lane = tid & 31, wid = tid >> 5;
    int mBase = blockIdx.y * 128, nBase = blockIdx.x * 128;
    int wm = (wid & 3) * 32, wn = (wid >> 2) * 64;
    int KC16 = K >> 4, KCS = K >> 5;

    float acc[2][8][4];
#pragma unroll
    for (int i = 0; i < 2; i++)
#pragma unroll
        for (int j = 0; j < 8; j++)
#pragma unroll
            for (int l = 0; l < 4; l++) acc[i][j][l] = 0.f;

    const uint4* Asrc = Ap + (size_t)blockIdx.y * KC16 * 512;
    const uint4* Bsrc = Bp + (size_t)blockIdx.x * KC16 * 512;

    auto do_copy = [&](int chS, int st) {
        uint4* dst = smem4 + st * 2048;
        uint32_t dA = (uint32_t)__cvta_generic_to_shared(dst + tid);
        const uint4* sA = Asrc + chS * 1024 + tid;
#pragma unroll
        for (int i = 0; i < 4; i++)
            cp16(dA + i * 256 * 16, sA + i * 256);
        uint32_t dB = (uint32_t)__cvta_generic_to_shared(dst + 1024 + tid);
        const uint4* sB = Bsrc + chS * 1024 + tid;
#pragma unroll
        for (int i = 0; i < 4; i++)
            cp16(dB + i * 256 * 16, sB + i * 256);
    };

    do_copy(0, 0); CP_COMMIT();
    if (1 < KCS) { do_copy(1, 1); }
    CP_COMMIT();

    int kq = lane & 3, sx = kq << 1;
    int rquad = lane >> 2;

    for (int ch = 0; ch < KCS; ch++) {
        if (ch >= KCS - 2)
            asm volatile("cp.async.wait_group 0;" ::: "memory");
        else
            asm volatile("cp.async.wait_group 1;" ::: "memory");
        __syncthreads();

        const uint4* As = smem4 + (ch % 3) * 2048;
        const uint4* Bs = As + 1024;

#pragma unroll
        for (int c2 = 0; c2 < 2; c2++) {
            int base = c2 * 512 + kq * 128;
            uint32_t ah[2][4], al[2][4];
#pragma unroll
            for (int mt = 0; mt < 2; mt++) {
                int rr = wm + rquad + mt * 16;
                uint4 v0 = As[base + (rr ^ sx)];
                uint4 v1 = As[base + ((rr + 8) ^ sx)];
                ah[mt][0] = v0.x; ah[mt][1] = v1.x;
                ah[mt][2] = v0.y; ah[mt][3] = v1.y;
                al[mt][0] = v0.z; al[mt][1] = v1.z;
                al[mt][2] = v0.w; al[mt][3] = v1.w;
            }
            uint32_t bh[8][2], bl[8][2];
#pragma unroll
            for (int j = 0; j < 8; j++) {
                int bn = wn + j * 8 + rquad;
                uint4 g = Bs[base + (bn ^ sx)];
                bh[j][0] = g.x; bh[j][1] = g.y;
                bl[j][0] = g.z; bl[j][1] = g.w;
            }
#pragma unroll
            for (int j = 0; j < 8; j++)
#pragma unroll
                for (int mt = 0; mt < 2; mt++)
                    mma_f16(acc[mt][j], ah[mt], bh[j]);
#pragma unroll
            for (int j = 0; j < 8; j++)
#pragma unroll
                for (int mt = 0; mt < 2; mt++)
                    mma_f16(acc[mt][j], al[mt], bh[j]);
#pragma unroll
            for (int j = 0; j < 8; j++)
#pragma unroll
                for (int mt = 0; mt < 2; mt++)
                    mma_f16(acc[mt][j], ah[mt], bl[j]);
        }

        if (ch + 2 < KCS) do_copy(ch + 2, (ch + 2) % 3);
        CP_COMMIT();
    }

    // ------------------------------ epilogue --------------------------------
#pragma unroll
    for (int mt = 0; mt < 2; mt++) {
        int r0loc = wm + mt * 16 + rquad;
        int gr0 = mBase + r0loc, gr1 = gr0 + 8;
        if (!PACK) {
#pragma unroll
            for (int nt = 0; nt < 8; nt++) {
                int c = nBase + wn + nt * 8 + kq * 2;
                if (c >= N) continue;
                float b0 = bias ? bias[c] : 0.f;
                float b1 = bias ? bias[c + 1] : 0.f;
                if (gr0 < M) {
                    float v0 = acc[mt][nt][0] + b0, v1 = acc[mt][nt][1] + b1;
                    if (doRelu) { v0 = fmaxf(v0, 0.f); v1 = fmaxf(v1, 0.f); }
                    *(float2*)&C[(size_t)gr0 * N + c] = make_float2(v0, v1);
                }
                if (gr1 < M) {
                    float v2 = acc[mt][nt][2] + b0, v3 = acc[mt][nt][3] + b1;
                    if (doRelu) { v2 = fmaxf(v2, 0.f); v3 = fmaxf(v3, 0.f); }
                    *(float2*)&C[(size_t)gr1 * N + c] = make_float2(v2, v3);
                }
            }
        } else {
#pragma unroll
            for (int ntp = 0; ntp < 8; ntp += 2) {
                int ncol = nBase + wn + ntp * 8 + kq * 2;
                int c16 = ncol >> 4;
                if (c16 >= KCpackTot) continue;
                float b0 = bias ? bias[ncol] : 0.f;
                float b1 = bias ? bias[ncol + 1] : 0.f;
                float b8 = bias ? bias[ncol + 8] : 0.f;
                float b9 = bias ? bias[ncol + 9] : 0.f;
                size_t dbase = ((size_t)blockIdx.y * KCpackTot + c16) * 512 +
                               kq * 128;
#pragma unroll
                for (int hlf = 0; hlf < 2; hlf++) {
                    int rloc = r0loc + hlf * 8;
                    int grow = mBase + rloc;
                    uint4 v = make_uint4(0u, 0u, 0u, 0u);
                    if (grow < M) {
                        float p0 = acc[mt][ntp][hlf * 2 + 0] + b0;
                        float p1 = acc[mt][ntp][hlf * 2 + 1] + b1;
                        float q0 = acc[mt][ntp + 1][hlf * 2 + 0] + b8;
                        float q1 = acc[mt][ntp + 1][hlf * 2 + 1] + b9;
                        if (doRelu) {
                            p0 = fmaxf(p0, 0.f); p1 = fmaxf(p1, 0.f);
                            q0 = fmaxf(q0, 0.f); q1 = fmaxf(q1, 0.f);
                        }
                        split_pair(p0, p1, v.x, v.z);
                        split_pair(q0, q1, v.y, v.w);
                    }
                    Cpack[dbase + (rloc ^ sx)] = v;
                }
            }
        }
    }
}

// --------------------------- GAT-specific kernels ---------------------------
__global__ void compute_al(const float* __restrict__ xp,
                           const float* __restrict__ asrc, const float* __restrict__ adst,
                           float* __restrict__ als, float* __restrict__ ald,
                           int H, int N) {
    int warp = (blockIdx.x * blockDim.x + threadIdx.x) >> 5;
    int lane = threadIdx.x & 31;
    if (warp >= N) return;
    int HC = H * CDIM;
    for (int h = 0; h < H; h++) {
        const float4* xr = (const float4*)(xp + (size_t)warp * HC + h * CDIM);
        const float4* ar = (const float4*)(asrc + h * CDIM);
        const float4* dr = (const float4*)(adst + h * CDIM);
        float s1 = 0.f, s2 = 0.f;
#pragma unroll
        for (int i = 0; i < 2; i++) {
            float4 x = xr[lane * 2 + i];
            float4 a = ar[lane * 2 + i];
            float4 dd = dr[lane * 2 + i];
            s1 += x.x * a.x + x.y * a.y + x.z * a.z + x.w * a.w;
            s2 += x.x * dd.x + x.y * dd.y + x.z * dd.z + x.w * dd.w;
        }
#pragma unroll
        for (int o = 16; o > 0; o >>= 1) {
            s1 += __shfl_down_sync(0xffffffffu, s1, o);
            s2 += __shfl_down_sync(0xffffffffu, s2, o);
        }
        if (lane == 0) { als[warp * H + h] = s1; ald[warp * H + h] = s2; }
    }
}

// fused logits + softmax + gather-aggregate; writes packed panels.
// H==2 fast path: both heads in one neighbor pass, 4-wide unroll (8 LDG MLP).
__global__ void gat_aggregate(const float* __restrict__ xp,
                              const float* __restrict__ als,
                              const float* __restrict__ ald,
                              const int* __restrict__ src, const int* __restrict__ sorted,
                              const int* __restrict__ off, const float* __restrict__ bias,
                              uint4* __restrict__ outP, int H) {
    int d = blockIdx.x, tid = threadIdx.x;
    int beg = off[d];
    int deg = off[d + 1] - beg;
    int HC = H * CDIM;
    __shared__ float sh[16];
    __shared__ float s_b[2];
    __shared__ float s_alpha[512];
    __shared__ int   s_row[256];
    __shared__ float s_out[512];

    if (H == 2 && deg <= 256) {
        int srow = 0;
        float lg0 = -1e30f, lg1 = -1e30f;
        float ald0 = ald[d * 2], ald1 = ald[d * 2 + 1];
        if (tid < deg) {
            srow = src[sorted[beg + tid]];
            s_row[tid] = srow;
            float v0 = als[srow * 2] + ald0;
            float v1 = als[srow * 2 + 1] + ald1;
            lg0 = v0 > 0.f ? v0 : 0.2f * v0;
            lg1 = v1 > 0.f ? v1 : 0.2f * v1;
        }
        float m0 = lg0, m1 = lg1;
#pragma unroll
        for (int o = 16; o > 0; o >>= 1) {
            m0 = fmaxf(m0, __shfl_down_sync(0xffffffffu, m0, o));
            m1 = fmaxf(m1, __shfl_down_sync(0xffffffffu, m1, o));
        }
        if ((tid & 31) == 0) { sh[tid >> 5] = m0; sh[8 + (tid >> 5)] = m1; }
        __syncthreads();
        if (tid < 8) {
            m0 = sh[tid]; m1 = sh[8 + tid];
#pragma unroll
            for (int o = 4; o > 0; o >>= 1) {
                m0 = fmaxf(m0, __shfl_down_sync(0xffu, m0, o));
                m1 = fmaxf(m1, __shfl_down_sync(0xffu, m1, o));
            }
            if (tid == 0) { s_b[0] = m0; s_b[1] = m1; }
        }
        __syncthreads();
        float g0 = s_b[0], g1 = s_b[1];

        float e0 = (tid < deg) ? __expf(lg0 - g0) : 0.f;
        float e1 = (tid < deg) ? __expf(lg1 - g1) : 0.f;
        s_alpha[tid] = e0;
        s_alpha[256 + tid] = e1;
        float t0 = e0, t1 = e1;
#pragma unroll
        for (int o = 16; o > 0; o >>= 1) {
            t0 += __shfl_down_sync(0xffffffffu, t0, o);
            t1 += __shfl_down_sync(0xffffffffu, t1, o);
        }
        if ((tid & 31) == 0) { sh[tid >> 5] = t0; sh[8 + (tid >> 5)] = t1; }
        __syncthreads();
        if (tid < 8) {
            t0 = sh[tid]; t1 = sh[8 + tid];
#pragma unroll
            for (int o = 4; o > 0; o >>= 1) {
                t0 += __shfl_down_sync(0xffu, t0, o);
                t1 += __shfl_down_sync(0xffu, t1, o);
            }
            if (tid == 0) { s_b[0] = t0; s_b[1] = t1; }
        }
        __syncthreads();
        float inv0 = 1.f / (s_b[0] + 1e-16f);
        float inv1 = 1.f / (s_b[1] + 1e-16f);

        // single neighbor pass, both heads, 4-wide (8 independent gathers)
        const float* xb = xp + tid;
        float a0 = 0.f, a1 = 0.f, a2 = 0.f, a3 = 0.f;
        float c0 = 0.f, c1 = 0.f, c2 = 0.f, c3 = 0.f;
        int j = 0;
        for (; j + 4 <= deg; j += 4) {
            size_t r0 = (size_t)s_row[j] * 512;
            size_t r1 = (size_t)s_row[j + 1] * 512;
            size_t r2 = (size_t)s_row[j + 2] * 512;
            size_t r3 = (size_t)s_row[j + 3] * 512;
            a0 += s_alpha[j] * xb[r0];
            c0 += s_alpha[256 + j] * xb[r0 + 256];
            a1 += s_alpha[j + 1] * xb[r1];
            c1 += s_alpha[256 + j + 1] * xb[r1 + 256];
            a2 += s_alpha[j + 2] * xb[r2];
            c2 += s_alpha[256 + j + 2] * xb[r2 + 256];
            a3 += s_alpha[j + 3] * xb[r3];
            c3 += s_alpha[256 + j + 3] * xb[r3 + 256];
        }
        for (; j < deg; j++) {
            size_t r0 = (size_t)s_row[j] * 512;
            a0 += s_alpha[j] * xb[r0];
            c0 += s_alpha[256 + j] * xb[r0 + 256];
        }
        s_out[tid] = fmaxf(((a0 + a1) + (a2 + a3)) * inv0 + bias[tid], 0.f);
        s_out[256 + tid] = fmaxf(((c0 + c1) + (c2 + c3)) * inv1 + bias[256 + tid], 0.f);
    } else if (deg <= 256) {
        int srow = 0;
        if (tid < deg) {
            srow = src[sorted[beg + tid]];
            s_row[tid] = srow;
        }
        for (int h = 0; h < H; h++) {
            float aldd = ald[d * H + h];
            float lg = -1e30f;
            if (tid < deg) {
                float v = als[srow * H + h] + aldd;
                lg = v > 0.f ? v : 0.2f * v;
            }
            float mx = lg;
#pragma unroll
            for (int o = 16; o > 0; o >>= 1)
                mx = fmaxf(mx, __shfl_down_sync(0xffffffffu, mx, o));
            if ((tid & 31) == 0) sh[tid >> 5] = mx;
            __syncthreads();
            if (tid < 8) {
                mx = sh[tid];
#pragma unroll
                for (int o = 4; o > 0; o >>= 1)
                    mx = fmaxf(mx, __shfl_down_sync(0xffu, mx, o));
                if (tid == 0) s_b[0] = mx;
            }
            __syncthreads();
            float gmax = s_b[0];

            float ee = (tid < deg) ? __expf(lg - gmax) : 0.f;
            s_alpha[tid] = ee;
            float sm = ee;
#pragma unroll
            for (int o = 16; o > 0; o >>= 1) sm += __shfl_down_sync(0xffffffffu, sm, o);
            if ((tid & 31) == 0) sh[tid >> 5] = sm;
            __syncthreads();
            if (tid < 8) {
                sm = sh[tid];
#pragma unroll
                for (int o = 4; o > 0; o >>= 1) sm += __shfl_down_sync(0xffu, sm, o);
                if (tid == 0) s_b[0] = sm;
            }
            __syncthreads();
            float inv = 1.f / (s_b[0] + 1e-16f);

            const float* xph = xp + h * CDIM + tid;
            float a0 = 0.f, a1 = 0.f, a2 = 0.f, a3 = 0.f;
            int j = 0;
            for (; j + 4 <= deg; j += 4) {
                a0 += s_alpha[j + 0] * xph[(size_t)s_row[j + 0] * HC];
                a1 += s_alpha[j + 1] * xph[(size_t)s_row[j + 1] * HC];
                a2 += s_alpha[j + 2] * xph[(size_t)s_row[j + 2] * HC];
                a3 += s_alpha[j + 3] * xph[(size_t)s_row[j + 3] * HC];
            }
            for (; j < deg; j++)
                a0 += s_alpha[j] * xph[(size_t)s_row[j] * HC];
            s_out[h * CDIM + tid] =
                fmaxf(((a0 + a1) + (a2 + a3)) * inv + bias[h * CDIM + tid], 0.f);
            __syncthreads();
        }
    } else {
        for (int h = 0; h < H; h++) {
            float aldd = ald[d * H + h];
            float mx = -1e30f;
            for (int i = tid; i < deg; i += 256) {
                int s = src[sorted[beg + i]];
                float v = als[s * H + h] + aldd;
                v = v > 0.f ? v : 0.2f * v;
                mx = fmaxf(mx, v);
            }
#pragma unroll
            for (int o = 16; o > 0; o >>= 1)
                mx = fmaxf(mx, __shfl_down_sync(0xffffffffu, mx, o));
            if ((tid & 31) == 0) sh[tid >> 5] = mx;
            __syncthreads();
            if (tid < 8) {
                mx = sh[tid];
#pragma unroll
                for (int o = 4; o > 0; o >>= 1)
                    mx = fmaxf(mx, __shfl_down_sync(0xffu, mx, o));
                if (tid == 0) s_b[0] = mx;
            }
            __syncthreads();
            float gmax = s_b[0];

            float sm = 0.f;
            for (int i = tid; i < deg; i += 256) {
                int s = src[sorted[beg + i]];
                float v = als[s * H + h] + aldd;
                v = v > 0.f ? v : 0.2f * v;
                sm += __expf(v - gmax);
            }
#pragma unroll
            for (int o = 16; o > 0; o >>= 1) sm += __shfl_down_sync(0xffffffffu, sm, o);
            if ((tid & 31) == 0) sh[tid >> 5] = sm;
            __syncthreads();
            if (tid < 8) {
                sm = sh[tid];
#pragma unroll
                for (int o = 4; o > 0; o >>= 1) sm += __shfl_down_sync(0xffu, sm, o);
                if (tid == 0) s_b[0] = sm;
            }
            __syncthreads();
            float inv = 1.f / (s_b[0] + 1e-16f);

            float acc = 0.f;
            for (int base = 0; base < deg; base += 256) {
                __syncthreads();
                int i = base + tid;
                if (i < deg) {
                    int s = src[sorted[beg + i]];
                    float v = als[s * H + h] + aldd;
                    v = v > 0.f ? v : 0.2f * v;
                    s_alpha[tid] = __expf(v - gmax) * inv;
                    s_row[tid]   = s;
                }
                __syncthreads();
                int lim = deg - base; if (lim > 256) lim = 256;
                for (int j = 0; j < lim; j++) {
                    acc += s_alpha[j] * xp[(size_t)s_row[j] * HC + h * CDIM + tid];
                }
            }
            s_out[h * CDIM + tid] = fmaxf(acc + bias[h * CDIM + tid], 0.f);
            __syncthreads();
        }
    }

    __syncthreads();
    int HC4 = HC >> 2;
    if (tid < HC4) {
        int c16 = tid >> 2, kq = tid & 3;
        int k0 = c16 * 16 + kq * 2;
        uint4 v;
        split_pair(s_out[k0], s_out[k0 + 1], v.x, v.z);
        split_pair(s_out[k0 + 8], s_out[k0 + 9], v.y, v.w);
        int t = d >> 7, dloc = d & 127;
        outP[((size_t)t * (HC >> 4) + c16) * 512 + kq * 128 + (dloc ^ (kq << 1))] = v;
    }
}

// --------------------------------- host -------------------------------------
static void run_gemm_f(cudaStream_t st, const uint4* Ap, const uint4* Bp,
                       const float* bias, float* C,
                       int M, int N, int K, bool relu) {
    dim3 grid((N + 127) / 128, (M + 127) / 128);
    mma_gemm_kernel<false><<<grid, 256, GEMM_SMEM, st>>>(
        M, N, K, Ap, Bp, bias, C, nullptr, 0, relu ? 1 : 0);
}

static void run_gemm_p(cudaStream_t st, const uint4* Ap, const uint4* Bp,
                       const float* bias, uint4* Cpack, int KCpackTot,
                       int M, int N, int K, bool relu) {
    dim3 grid((N + 127) / 128, (M + 127) / 128);
    mma_gemm_kernel<true><<<grid, 256, GEMM_SMEM, st>>>(
        M, N, K, Ap, Bp, bias, nullptr, Cpack, KCpackTot, relu ? 1 : 0);
}

static void run_pack_w(cudaStream_t st, const float* W, int K, int N, uint4* out) {
    int total = ((N + 127) / 128) * (K >> 4) * 512;
    pack_w_kernel<<<(total + 255) / 256, 256, 0, st>>>(W, K, N, out, total);
}

struct Tower {
    float *bufA;
    uint4 *xsP, *aggBP, *aggCP, *m1P, *m2P, *finP;
    float *als, *ald;
    int *deg, *off, *cur, *sorted;
    uint4 *pW1, *pW2, *pL1, *pL2, *pL3;
};

static void run_tower(cudaStream_t st, cudaStream_t stS,
                      cudaEvent_t evW1, cudaEvent_t evSort, cudaEvent_t evPk,
                      const Tower& T,
                      const float* x, int N, int E, const int* src, const int* dst,
                      const float* W1, const float* a1s, const float* a1d, const float* b1,
                      const float* W2, const float* a2s, const float* a2d, const float* b2,
                      const float* lw1, const float* lb1, const float* lw2, const float* lb2,
                      const float* lw3, const float* lb3) {
    int NT = (N + 127) / 128;
    int xTotal = NT * 16 * 512;
    int alGrid = (N * 32 + 255) / 256;

    // fork stream: W1 pack first (GEMM1 dep), then sort, then remaining packs
    run_pack_w(stS, W1, 256, 512, T.pW1);
    cudaEventRecord(evW1, stS);
    zero_int_kernel<<<(N + 256) / 256, 256, 0, stS>>>(T.deg, N + 1);
    zero_int_kernel<<<(N + 255) / 256, 256, 0, stS>>>(T.cur, N);
    hist_kernel<<<(E + 255) / 256, 256, 0, stS>>>(dst, E, T.deg);
    scan_kernel<<<1, 1024, 0, stS>>>(T.deg, T.off, N);
    scatter_kernel<<<(E + 255) / 256, 256, 0, stS>>>(dst, E, T.off, T.cur, T.sorted);
    cudaEventRecord(evSort, stS);
    run_pack_w(stS, W2, 512, 256, T.pW2);
    run_pack_w(stS, lw1, 256, 256, T.pL1);
    run_pack_w(stS, lw2, 256, 128, T.pL2);
    run_pack_w(stS, lw3, 128, 64, T.pL3);
    cudaEventRecord(evPk, stS);

    // main stream
    pack_x_kernel<<<(xTotal + 255) / 256, 256, 0, st>>>(x, N, 256, T.xsP, xTotal);
    cudaStreamWaitEvent(st, evW1, 0);
    run_gemm_f(st, T.xsP, T.pW1, nullptr, T.bufA, N, 512, 256, false);

    compute_al<<<alGrid, 256, 0, st>>>(T.bufA, a1s, a1d, T.als, T.ald, 2, N);
    cudaStreamWaitEvent(st, evSort, 0);
    gat_aggregate<<<N, 256, 0, st>>>(T.bufA, T.als, T.ald, src, T.sorted, T.off,
                                     b1, T.aggBP, 2);

    cudaStreamWaitEvent(st, evPk, 0);
    run_gemm_f(st, T.aggBP, T.pW2, nullptr, T.bufA, N, 256, 512, false);
    compute_al<<<alGrid, 256, 0, st>>>(T.bufA, a2s, a2d, T.als, T.ald, 1, N);
    gat_aggregate<<<N, 256, 0, st>>>(T.bufA, T.als, T.ald, src, T.sorted, T.off,
                                     b2, T.aggCP, 1);

    run_gemm_p(st, T.aggCP, T.pL1, lb1, T.m1P, 16, N, 256, 256, true);
    run_gemm_p(st, T.m1P, T.pL2, lb2, T.m2P, 8, N, 128, 256, true);
    run_gemm_p(st, T.m2P, T.pL3, lb3, T.finP, 4, N, 64, 128, true);
}

#define GSA(p, s) cudaGetSymbolAddress((void**)&(p), s)

extern "C" void kernel_launch(void* const* d_in, const int* in_sizes, int n_in,
                              void* d_out, int out_size) {
    const float* x_m  = (const float*)d_in[0];
    const float* x_d  = (const float*)d_in[1];
    const int*   eix  = (const int*)d_in[2];
    const int*   eiy  = (const int*)d_in[3];
    const float* Wx1 = (const float*)d_in[4];
    const float* ax1s = (const float*)d_in[5];
    const float* ax1d = (const float*)d_in[6];
    const float* bx1 = (const float*)d_in[7];
    const float* Wx2 = (const float*)d_in[8];
    const float* ax2s = (const float*)d_in[9];
    const float* ax2d = (const float*)d_in[10];
    const float* bx2 = (const float*)d_in[11];
    const float* Wy1 = (const float*)d_in[12];
    const float* ay1s = (const float*)d_in[13];
    const float* ay1d = (const float*)d_in[14];
    const float* by1 = (const float*)d_in[15];
    const float* Wy2 = (const float*)d_in[16];
    const float* ay2s = (const float*)d_in[17];
    const float* ay2d = (const float*)d_in[18];
    const float* by2 = (const float*)d_in[19];
    const float* lwx1 = (const float*)d_in[20];
    const float* lbx1 = (const float*)d_in[21];
    const float* lwx2 = (const float*)d_in[22];
    const float* lbx2 = (const float*)d_in[23];
    const float* lwx3 = (const float*)d_in[24];
    const float* lbx3 = (const float*)d_in[25];
    const float* lwy1 = (const float*)d_in[26];
    const float* lby1 = (const float*)d_in[27];
    const float* lwy2 = (const float*)d_in[28];
    const float* lby2 = (const float*)d_in[29];
    const float* lwy3 = (const float*)d_in[30];
    const float* lby3 = (const float*)d_in[31];

    int M  = in_sizes[0] / 256;
    int D  = in_sizes[1] / 256;
    int EX = in_sizes[2] / 2;
    int EY = in_sizes[3] / 2;

    static bool s_init = false;
    static cudaStream_t sY, sSX, sSY;
    static cudaEvent_t evRoot, evY;
    static cudaEvent_t evW1X, evSortX, evPkX, evW1Y, evSortY, evPkY;
    if (!s_init) {
        cudaStreamCreateWithFlags(&sY, cudaStreamNonBlocking);
        cudaStreamCreateWithFlags(&sSX, cudaStreamNonBlocking);
        cudaStreamCreateWithFlags(&sSY, cudaStreamNonBlocking);
        cudaEventCreateWithFlags(&evRoot, cudaEventDisableTiming);
        cudaEventCreateWithFlags(&evY, cudaEventDisableTiming);
        cudaEventCreateWithFlags(&evW1X, cudaEventDisableTiming);
        cudaEventCreateWithFlags(&evSortX, cudaEventDisableTiming);
        cudaEventCreateWithFlags(&evPkX, cudaEventDisableTiming);
        cudaEventCreateWithFlags(&evW1Y, cudaEventDisableTiming);
        cudaEventCreateWithFlags(&evSortY, cudaEventDisableTiming);
        cudaEventCreateWithFlags(&evPkY, cudaEventDisableTiming);
        cudaFuncSetAttribute(mma_gemm_kernel<false>,
                             cudaFuncAttributeMaxDynamicSharedMemorySize, GEMM_SMEM);
        cudaFuncSetAttribute(mma_gemm_kernel<true>,
                             cudaFuncAttributeMaxDynamicSharedMemorySize, GEMM_SMEM);
        s_init = true;
    }

    Tower TX, TY;
    GSA(TX.bufA, g_bufA);
    GSA(TX.xsP, g_xsP); GSA(TX.aggBP, g_aggBP);
    GSA(TX.aggCP, g_aggCP); GSA(TX.m1P, g_m1P); GSA(TX.m2P, g_m2P);
    GSA(TX.finP, g_finP);
    GSA(TX.als, g_als); GSA(TX.ald, g_ald);
    GSA(TX.deg, g_deg); GSA(TX.off, g_off); GSA(TX.cur, g_cur);
    GSA(TX.sorted, g_sorted);
    GSA(TX.pW1, g_pW1); GSA(TX.pW2, g_pW2);
    GSA(TX.pL1, g_pL1); GSA(TX.pL2, g_pL2); GSA(TX.pL3, g_pL3);

    GSA(TY.bufA, g2_bufA);
    GSA(TY.xsP, g2_xsP); GSA(TY.aggBP, g2_aggBP);
    GSA(TY.aggCP, g2_aggCP); GSA(TY.m1P, g2_m1P); GSA(TY.m2P, g2_m2P);
    GSA(TY.finP, g2_finP);
    GSA(TY.als, g2_als); GSA(TY.ald, g2_ald);
    GSA(TY.deg, g2_deg); GSA(TY.off, g2_off); GSA(TY.cur, g2_cur);
    GSA(TY.sorted, g2_sorted);
    GSA(TY.pW1, g2_pW1); GSA(TY.pW2, g2_pW2);
    GSA(TY.pL1, g2_pL1); GSA(TY.pL2, g2_pL2); GSA(TY.pL3, g2_pL3);

    cudaEventRecord(evRoot, 0);
    cudaStreamWaitEvent(sY, evRoot, 0);
    cudaStreamWaitEvent(sSX, evRoot, 0);
    cudaStreamWaitEvent(sSY, evRoot, 0);

    run_tower(0, sSX, evW1X, evSortX, evPkX, TX, x_m, M, EX, eix, eix + EX,
              Wx1, ax1s, ax1d, bx1, Wx2, ax2s, ax2d, bx2,
              lwx1, lbx1, lwx2, lbx2, lwx3, lbx3);
    run_tower(sY, sSY, evW1Y, evSortY, evPkY, TY, x_d, D, EY, eiy, eiy + EY,
              Wy1, ay1s, ay1d, by1, Wy2, ay2s, ay2d, by2,
              lwy1, lby1, lwy2, lby2, lwy3, lby3);

    cudaEventRecord(evY, sY);
    cudaStreamWaitEvent(0, evY, 0);

    run_gemm_f(0, TX.finP, TY.finP, nullptr, (float*)d_out, M, D, 64, false);
}

// round 17
// speedup vs baseline: 1.2048x; 1.0874x over previous
#include <cuda_runtime.h>
#include <cuda_fp16.h>
#include <math.h>
#include <stdint.h>

// ----------------------------------------------------------------------------
// Problem constants: M=D=10000, FG=FD=256, H1=2, K=64, E=320000
// ----------------------------------------------------------------------------
#define MAXN 10000
#define MAXE 320000
#define CDIM 256

// ------------------------- device scratch (no mallocs) ----------------------
// Tower X
__device__ float  g_bufA[MAXN * 512];
__device__ uint4  g_xsP[650000];
__device__ uint4  g_aggBP[1300000];
__device__ uint4  g_aggCP[650000];
__device__ uint4  g_m1P[650000];
__device__ uint4  g_m2P[330000];
__device__ uint4  g_finP[165000];
__device__ float  g_als[MAXN * 2];
__device__ float  g_ald[MAXN * 2];
__device__ int    g_deg[MAXN + 1];
__device__ int    g_off[MAXN + 1];
__device__ int    g_cur[MAXN];
__device__ int    g_sorted[MAXE];
__device__ uint4  g_pW1[32768];
__device__ uint4  g_pW2[32768];
__device__ uint4  g_pL1[16384];
__device__ uint4  g_pL2[8192];
__device__ uint4  g_pL3[4096];
// Tower Y
__device__ float  g2_bufA[MAXN * 512];
__device__ uint4  g2_xsP[650000];
__device__ uint4  g2_aggBP[1300000];
__device__ uint4  g2_aggCP[650000];
__device__ uint4  g2_m1P[650000];
__device__ uint4  g2_m2P[330000];
__device__ uint4  g2_finP[165000];
__device__ float  g2_als[MAXN * 2];
__device__ float  g2_ald[MAXN * 2];
__device__ int    g2_deg[MAXN + 1];
__device__ int    g2_off[MAXN + 1];
__device__ int    g2_cur[MAXN];
__device__ int    g2_sorted[MAXE];
__device__ uint4  g2_pW1[32768];
__device__ uint4  g2_pW2[32768];
__device__ uint4  g2_pL1[16384];
__device__ uint4  g2_pL2[8192];
__device__ uint4  g2_pL3[4096];

// ------------------------------ helpers -------------------------------------
__device__ __forceinline__ void split_pair(float a, float b,
                                           uint32_t& hi, uint32_t& lo) {
    __half ha = __float2half_rn(a), hb = __float2half_rn(b);
    float ra = a - __half2float(ha), rb = b - __half2float(hb);
    __half2 h = __halves2half2(ha, hb);
    __half2 l = __floats2half2_rn(ra, rb);
    hi = *(uint32_t*)&h;
    lo = *(uint32_t*)&l;
}

__device__ __forceinline__ void mma_f16(float* c, const uint32_t* a,
                                        const uint32_t* b) {
    asm volatile(
        "mma.sync.aligned.m16n8k16.row.col.f32.f16.f16.f32 "
        "{%0,%1,%2,%3}, {%4,%5,%6,%7}, {%8,%9}, {%0,%1,%2,%3};"
        : "+f"(c[0]), "+f"(c[1]), "+f"(c[2]), "+f"(c[3])
        : "r"(a[0]), "r"(a[1]), "r"(a[2]), "r"(a[3]), "r"(b[0]), "r"(b[1]));
}

__device__ __forceinline__ void cp16(uint32_t dst, const void* src) {
    asm volatile("cp.async.cg.shared.global [%0], [%1], 16;"
                 :: "r"(dst), "l"(src));
}
#define CP_COMMIT() asm volatile("cp.async.commit_group;" ::: "memory")

__device__ __forceinline__ void st_cs_f2(float* p, float v0, float v1) {
    asm volatile("st.global.cs.v2.f32 [%0], {%1, %2};"
                 :: "l"(p), "f"(v0), "f"(v1) : "memory");
}

// ------------------------------ tiny kernels --------------------------------
__global__ void zero_int_kernel(int* p, int n) {
    int i = blockIdx.x * blockDim.x + threadIdx.x;
    if (i < n) p[i] = 0;
}

__global__ void hist_kernel(const int* __restrict__ dst, int E, int* __restrict__ deg) {
    int e = blockIdx.x * blockDim.x + threadIdx.x;
    if (e < E) atomicAdd(&deg[dst[e]], 1);
}

__global__ void scan_kernel(const int* __restrict__ deg, int* __restrict__ off, int n) {
    const int T = 1024;
    int t = threadIdx.x;
    int chunk = (n + T - 1) / T;
    int b = t * chunk;
    int e2 = b + chunk; if (e2 > n) e2 = n;
    int s = 0;
    for (int i = b; i < e2; i++) s += deg[i];
    __shared__ int sh[T];
    sh[t] = s;
    __syncthreads();
    for (int d2 = 1; d2 < T; d2 <<= 1) {
        int v = (t >= d2) ? sh[t - d2] : 0;
        __syncthreads();
        sh[t] += v;
        __syncthreads();
    }
    int run = (t == 0) ? 0 : sh[t - 1];
    for (int i = b; i < e2; i++) { off[i] = run; run += deg[i]; }
    if (t == 0) off[n] = sh[T - 1];
}

__global__ void scatter_kernel(const int* __restrict__ dst, int E,
                               const int* __restrict__ off, int* __restrict__ cur,
                               int* __restrict__ sorted) {
    int e = blockIdx.x * blockDim.x + threadIdx.x;
    if (e < E) {
        int d = dst[e];
        int p = atomicAdd(&cur[d], 1);
        sorted[off[d] + p] = e;
    }
}

__global__ void pack_x_kernel(const float* __restrict__ X, int Nrows, int K,
                              uint4* __restrict__ out, int total) {
    int idx = blockIdx.x * blockDim.x + threadIdx.x;
    if (idx >= total) return;
    int KC16 = K >> 4;
    int t = idx / (KC16 * 512);
    int rem = idx - t * (KC16 * 512);
    int c16 = rem >> 9, f = rem & 511;
    int kq = f >> 7, pos = f & 127;
    int r = pos ^ (kq << 1);
    int row = t * 128 + r;
    int k0 = c16 * 16 + kq * 2;
    uint4 v = make_uint4(0u, 0u, 0u, 0u);
    if (row < Nrows) {
        const float* p = &X[(size_t)row * K];
        split_pair(p[k0], p[k0 + 1], v.x, v.z);
        split_pair(p[k0 + 8], p[k0 + 9], v.y, v.w);
    }
    out[idx] = v;
}

__global__ void pack_w_kernel(const float* __restrict__ W, int K, int N,
                              uint4* __restrict__ out, int total) {
    int idx = blockIdx.x * blockDim.x + threadIdx.x;
    if (idx >= total) return;
    int KC16 = K >> 4;
    int t = idx / (KC16 * 512);
    int rem = idx - t * (KC16 * 512);
    int c16 = rem >> 9, f = rem & 511;
    int kq = f >> 7, pos = f & 127;
    int n = t * 128 + (pos ^ (kq << 1));
    int k0 = c16 * 16 + kq * 2;
    uint4 v = make_uint4(0u, 0u, 0u, 0u);
    if (n < N) {
        split_pair(W[(size_t)k0 * N + n], W[(size_t)(k0 + 1) * N + n], v.x, v.z);
        split_pair(W[(size_t)(k0 + 8) * N + n], W[(size_t)(k0 + 9) * N + n], v.y, v.w);
    }
    out[idx] = v;
}

// ------------------------ fp16x3 GEMM via mma.sync --------------------------
#define GEMM_SMEM (3 * 2048 * 16)

template <bool PACK>
__global__ __launch_bounds__(256, 2)
void mma_gemm_kernel(int M, int N, int K,
                     const uint4* __restrict__ Ap, const uint4* __restrict__ Bp,
                     const float* __restrict__ bias,
                     float* __restrict__ C,
                     uint4* __restrict__ Cpack, int KCpackTot,
                     int doRelu) {
    extern __shared__ uint4 smem4[];
    int tid = threadIdx.x, lane = tid & 31, wid = tid >> 5;
    int mBase = blockIdx.y * 128, nBase = blockIdx.x * 128;
    int wm = (wid & 3) * 32, wn = (wid >> 2) * 64;
    int KC16 = K >> 4, KCS = K >> 5;

    float acc[2][8][4];
#pragma unroll
    for (int i = 0; i < 2; i++)
#pragma unroll
        for (int j = 0; j < 8; j++)
#pragma unroll
            for (int l = 0; l < 4; l++) acc[i][j][l] = 0.f;

    const uint4* Asrc = Ap + (size_t)blockIdx.y * KC16 * 512;
    const uint4* Bsrc = Bp + (size_t)blockIdx.x * KC16 * 512;

    auto do_copy = [&](int chS, int st) {
        uint4* dst = smem4 + st * 2048;
        uint32_t dA = (uint32_t)__cvta_generic_to_shared(dst + tid);
        const uint4* sA = Asrc + chS * 1024 + tid;
#pragma unroll
        for (int i = 0; i < 4; i++)
            cp16(dA + i * 256 * 16, sA + i * 256);
        uint32_t dB = (uint32_t)__cvta_generic_to_shared(dst + 1024 + tid);
        const uint4* sB = Bsrc + chS * 1024 + tid;
#pragma unroll
        for (int i = 0; i < 4; i++)
            cp16(dB + i * 256 * 16, sB + i * 256);
    };

    do_copy(0, 0); CP_COMMIT();
    if (1 < KCS) { do_copy(1, 1); }
    CP_COMMIT();

    int kq = lane & 3, sx = kq << 1;
    int rquad = lane >> 2;

    for (int ch = 0; ch < KCS; ch++) {
        if (ch >= KCS - 2)
            asm volatile("cp.async.wait_group 0;" ::: "memory");
        else
            asm volatile("cp.async.wait_group 1;" ::: "memory");
        __syncthreads();

        const uint4* As = smem4 + (ch % 3) * 2048;
        const uint4* Bs = As + 1024;

#pragma unroll
        for (int c2 = 0; c2 < 2; c2++) {
            int base = c2 * 512 + kq * 128;
            uint32_t ah[2][4], al[2][4];
#pragma unroll
            for (int mt = 0; mt < 2; mt++) {
                int rr = wm + rquad + mt * 16;
                uint4 v0 = As[base + (rr ^ sx)];
                uint4 v1 = As[base + ((rr + 8) ^ sx)];
                ah[mt][0] = v0.x; ah[mt][1] = v1.x;
                ah[mt][2] = v0.y; ah[mt][3] = v1.y;
                al[mt][0] = v0.z; al[mt][1] = v1.z;
                al[mt][2] = v0.w; al[mt][3] = v1.w;
            }
            uint32_t bh[8][2], bl[8][2];
#pragma unroll
            for (int j = 0; j < 8; j++) {
                int bn = wn + j * 8 + rquad;
                uint4 g = Bs[base + (bn ^ sx)];
                bh[j][0] = g.x; bh[j][1] = g.y;
                bl[j][0] = g.z; bl[j][1] = g.w;
            }
#pragma unroll
            for (int j = 0; j < 8; j++)
#pragma unroll
                for (int mt = 0; mt < 2; mt++)
                    mma_f16(acc[mt][j], ah[mt], bh[j]);
#pragma unroll
            for (int j = 0; j < 8; j++)
#pragma unroll
                for (int mt = 0; mt < 2; mt++)
                    mma_f16(acc[mt][j], al[mt], bh[j]);
#pragma unroll
            for (int j = 0; j < 8; j++)
#pragma unroll
                for (int mt = 0; mt < 2; mt++)
                    mma_f16(acc[mt][j], ah[mt], bl[j]);
        }

        if (ch + 2 < KCS) do_copy(ch + 2, (ch + 2) % 3);
        CP_COMMIT();
    }

    // ------------------------------ epilogue --------------------------------
#pragma unroll
    for (int mt = 0; mt < 2; mt++) {
        int r0loc = wm + mt * 16 + rquad;
        int gr0 = mBase + r0loc, gr1 = gr0 + 8;
        if (!PACK) {
#pragma unroll
            for (int nt = 0; nt < 8; nt++) {
                int c = nBase + wn + nt * 8 + kq * 2;
                if (c >= N) continue;
                float b0 = bias ? bias[c] : 0.f;
                float b1 = bias ? bias[c + 1] : 0.f;
                if (gr0 < M) {
                    float v0 = acc[mt][nt][0] + b0, v1 = acc[mt][nt][1] + b1;
                    if (doRelu) { v0 = fmaxf(v0, 0.f); v1 = fmaxf(v1, 0.f); }
                    *(float2*)&C[(size_t)gr0 * N + c] = make_float2(v0, v1);
                }
                if (gr1 < M) {
                    float v2 = acc[mt][nt][2] + b0, v3 = acc[mt][nt][3] + b1;
                    if (doRelu) { v2 = fmaxf(v2, 0.f); v3 = fmaxf(v3, 0.f); }
                    *(float2*)&C[(size_t)gr1 * N + c] = make_float2(v2, v3);
                }
            }
        } else {
#pragma unroll
            for (int ntp = 0; ntp < 8; ntp += 2) {
                int ncol = nBase + wn + ntp * 8 + kq * 2;
                int c16 = ncol >> 4;
                if (c16 >= KCpackTot) continue;
                float b0 = bias ? bias[ncol] : 0.f;
                float b1 = bias ? bias[ncol + 1] : 0.f;
                float b8 = bias ? bias[ncol + 8] : 0.f;
                float b9 = bias ? bias[ncol + 9] : 0.f;
                size_t dbase = ((size_t)blockIdx.y * KCpackTot + c16) * 512 +
                               kq * 128;
#pragma unroll
                for (int hlf = 0; hlf < 2; hlf++) {
                    int rloc = r0loc + hlf * 8;
                    int grow = mBase + rloc;
                    uint4 v = make_uint4(0u, 0u, 0u, 0u);
                    if (grow < M) {
                        float p0 = acc[mt][ntp][hlf * 2 + 0] + b0;
                        float p1 = acc[mt][ntp][hlf * 2 + 1] + b1;
                        float q0 = acc[mt][ntp + 1][hlf * 2 + 0] + b8;
                        float q1 = acc[mt][ntp + 1][hlf * 2 + 1] + b9;
                        if (doRelu) {
                            p0 = fmaxf(p0, 0.f); p1 = fmaxf(p1, 0.f);
                            q0 = fmaxf(q0, 0.f); q1 = fmaxf(q1, 0.f);
                        }
                        split_pair(p0, p1, v.x, v.z);
                        split_pair(q0, q1, v.y, v.w);
                    }
                    Cpack[dbase + (rloc ^ sx)] = v;
                }
            }
        }
    }
}

// -------------------- final GEMM (K=64, 2-term, streaming) ------------------
// out = A @ B^T with A,B fp16 panels; both operands ReLU outputs (>=0) so the
// 2-term split is safe (R9-measured rel_err ~8e-5). No bias/relu. st.global.cs.
#define FGEMM_SMEM (2 * 2048 * 16)

__global__ __launch_bounds__(256, 2)
void mma_gemm_final(int M, int N,
                    const uint4* __restrict__ Ap, const uint4* __restrict__ Bp,
                    float* __restrict__ C) {
    extern __shared__ uint4 smem4[];
    int tid = threadIdx.x, lane = tid & 31, wid = tid >> 5;
    int mBase = blockIdx.y * 128, nBase = blockIdx.x * 128;
    int wm = (wid & 3) * 32, wn = (wid >> 2) * 64;
    const int KC16 = 4;

    float acc[2][8][4];
#pragma unroll
    for (int i = 0; i < 2; i++)
#pragma unroll
        for (int j = 0; j < 8; j++)
#pragma unroll
            for (int l = 0; l < 4; l++) acc[i][j][l] = 0.f;

    const uint4* Asrc = Ap + (size_t)blockIdx.y * KC16 * 512;
    const uint4* Bsrc = Bp + (size_t)blockIdx.x * KC16 * 512;

#pragma unroll
    for (int st = 0; st < 2; st++) {
        uint4* dst = smem4 + st * 2048;
        uint32_t dA = (uint32_t)__cvta_generic_to_shared(dst + tid);
        const uint4* sA = Asrc + st * 1024 + tid;
#pragma unroll
        for (int i = 0; i < 4; i++)
            cp16(dA + i * 256 * 16, sA + i * 256);
        uint32_t dB = (uint32_t)__cvta_generic_to_shared(dst + 1024 + tid);
        const uint4* sB = Bsrc + st * 1024 + tid;
#pragma unroll
        for (int i = 0; i < 4; i++)
            cp16(dB + i * 256 * 16, sB + i * 256);
        CP_COMMIT();
    }

    int kq = lane & 3, sx = kq << 1;
    int rquad = lane >> 2;

#pragma unroll
    for (int ch = 0; ch < 2; ch++) {
        if (ch == 0)
            asm volatile("cp.async.wait_group 1;" ::: "memory");
        else
            asm volatile("cp.async.wait_group 0;" ::: "memory");
        __syncthreads();

        const uint4* As = smem4 + ch * 2048;
        const uint4* Bs = As + 1024;

#pragma unroll
        for (int c2 = 0; c2 < 2; c2++) {
            int base = c2 * 512 + kq * 128;
            uint32_t ah[2][4], al[2][4];
#pragma unroll
            for (int mt = 0; mt < 2; mt++) {
                int rr = wm + rquad + mt * 16;
                uint4 v0 = As[base + (rr ^ sx)];
                uint4 v1 = As[base + ((rr + 8) ^ sx)];
                ah[mt][0] = v0.x; ah[mt][1] = v1.x;
                ah[mt][2] = v0.y; ah[mt][3] = v1.y;
                al[mt][0] = v0.z; al[mt][1] = v1.z;
                al[mt][2] = v0.w; al[mt][3] = v1.w;
            }
            uint32_t bh[8][2];
#pragma unroll
            for (int j = 0; j < 8; j++) {
                int bn = wn + j * 8 + rquad;
                uint4 g = Bs[base + (bn ^ sx)];
                bh[j][0] = g.x; bh[j][1] = g.y;
            }
#pragma unroll
            for (int j = 0; j < 8; j++)
#pragma unroll
                for (int mt = 0; mt < 2; mt++)
                    mma_f16(acc[mt][j], ah[mt], bh[j]);
#pragma unroll
            for (int j = 0; j < 8; j++)
#pragma unroll
                for (int mt = 0; mt < 2; mt++)
                    mma_f16(acc[mt][j], al[mt], bh[j]);
        }
    }

    // streaming epilogue, no bias/relu
#pragma unroll
    for (int mt = 0; mt < 2; mt++) {
        int gr0 = mBase + wm + mt * 16 + rquad;
        int gr1 = gr0 + 8;
#pragma unroll
        for (int nt = 0; nt < 8; nt++) {
            int c = nBase + wn + nt * 8 + kq * 2;
            if (c >= N) continue;
            if (gr0 < M)
                st_cs_f2(&C[(size_t)gr0 * N + c], acc[mt][nt][0], acc[mt][nt][1]);
            if (gr1 < M)
                st_cs_f2(&C[(size_t)gr1 * N + c], acc[mt][nt][2], acc[mt][nt][3]);
        }
    }
}

// --------------------------- GAT-specific kernels ---------------------------
__global__ void compute_al(const float* __restrict__ xp,
                           const float* __restrict__ asrc, const float* __restrict__ adst,
                           float* __restrict__ als, float* __restrict__ ald,
                           int H, int N) {
    int warp = (blockIdx.x * blockDim.x + threadIdx.x) >> 5;
    int lane = threadIdx.x & 31;
    if (warp >= N) return;
    int HC = H * CDIM;
    for (int h = 0; h < H; h++) {
        const float4* xr = (const float4*)(xp + (size_t)warp * HC + h * CDIM);
        const float4* ar = (const float4*)(asrc + h * CDIM);
        const float4* dr = (const float4*)(adst + h * CDIM);
        float s1 = 0.f, s2 = 0.f;
#pragma unroll
        for (int i = 0; i < 2; i++) {
            float4 x = xr[lane * 2 + i];
            float4 a = ar[lane * 2 + i];
            float4 dd = dr[lane * 2 + i];
            s1 += x.x * a.x + x.y * a.y + x.z * a.z + x.w * a.w;
            s2 += x.x * dd.x + x.y * dd.y + x.z * dd.z + x.w * dd.w;
        }
#pragma unroll
        for (int o = 16; o > 0; o >>= 1) {
            s1 += __shfl_down_sync(0xffffffffu, s1, o);
            s2 += __shfl_down_sync(0xffffffffu, s2, o);
        }
        if (lane == 0) { als[warp * H + h] = s1; ald[warp * H + h] = s2; }
    }
}

__global__ void gat_aggregate(const float* __restrict__ xp,
                              const float* __restrict__ als,
                              const float* __restrict__ ald,
                              const int* __restrict__ src, const int* __restrict__ sorted,
                              const int* __restrict__ off, const float* __restrict__ bias,
                              uint4* __restrict__ outP, int H) {
    int d = blockIdx.x, tid = threadIdx.x;
    int beg = off[d];
    int deg = off[d + 1] - beg;
    int HC = H * CDIM;
    __shared__ float sh[16];
    __shared__ float s_b[2];
    __shared__ float s_alpha[512];
    __shared__ int   s_row[256];
    __shared__ float s_out[512];

    if (H == 2 && deg <= 256) {
        int srow = 0;
        float lg0 = -1e30f, lg1 = -1e30f;
        float ald0 = ald[d * 2], ald1 = ald[d * 2 + 1];
        if (tid < deg) {
            srow = src[sorted[beg + tid]];
            s_row[tid] = srow;
            float v0 = als[srow * 2] + ald0;
            float v1 = als[srow * 2 + 1] + ald1;
            lg0 = v0 > 0.f ? v0 : 0.2f * v0;
            lg1 = v1 > 0.f ? v1 : 0.2f * v1;
        }
        float m0 = lg0, m1 = lg1;
#pragma unroll
        for (int o = 16; o > 0; o >>= 1) {
            m0 = fmaxf(m0, __shfl_down_sync(0xffffffffu, m0, o));
            m1 = fmaxf(m1, __shfl_down_sync(0xffffffffu, m1, o));
        }
        if ((tid & 31) == 0) { sh[tid >> 5] = m0; sh[8 + (tid >> 5)] = m1; }
        __syncthreads();
        if (tid < 8) {
            m0 = sh[tid]; m1 = sh[8 + tid];
#pragma unroll
            for (int o = 4; o > 0; o >>= 1) {
                m0 = fmaxf(m0, __shfl_down_sync(0xffu, m0, o));
                m1 = fmaxf(m1, __shfl_down_sync(0xffu, m1, o));
            }
            if (tid == 0) { s_b[0] = m0; s_b[1] = m1; }
        }
        __syncthreads();
        float g0 = s_b[0], g1 = s_b[1];

        float e0 = (tid < deg) ? __expf(lg0 - g0) : 0.f;
        float e1 = (tid < deg) ? __expf(lg1 - g1) : 0.f;
        s_alpha[tid] = e0;
        s_alpha[256 + tid] = e1;
        float t0 = e0, t1 = e1;
#pragma unroll
        for (int o = 16; o > 0; o >>= 1) {
            t0 += __shfl_down_sync(0xffffffffu, t0, o);
            t1 += __shfl_down_sync(0xffffffffu, t1, o);
        }
        if ((tid & 31) == 0) { sh[tid >> 5] = t0; sh[8 + (tid >> 5)] = t1; }
        __syncthreads();
        if (tid < 8) {
            t0 = sh[tid]; t1 = sh[8 + tid];
#pragma unroll
            for (int o = 4; o > 0; o >>= 1) {
                t0 += __shfl_down_sync(0xffu, t0, o);
                t1 += __shfl_down_sync(0xffu, t1, o);
            }
            if (tid == 0) { s_b[0] = t0; s_b[1] = t1; }
        }
        __syncthreads();
        float inv0 = 1.f / (s_b[0] + 1e-16f);
        float inv1 = 1.f / (s_b[1] + 1e-16f);

        const float* xb = xp + tid;
        float a0 = 0.f, a1 = 0.f, a2 = 0.f, a3 = 0.f;
        float c0 = 0.f, c1 = 0.f, c2 = 0.f, c3 = 0.f;
        int j = 0;
        for (; j + 4 <= deg; j += 4) {
            size_t r0 = (size_t)s_row[j] * 512;
            size_t r1 = (size_t)s_row[j + 1] * 512;
            size_t r2 = (size_t)s_row[j + 2] * 512;
            size_t r3 = (size_t)s_row[j + 3] * 512;
            a0 += s_alpha[j] * xb[r0];
            c0 += s_alpha[256 + j] * xb[r0 + 256];
            a1 += s_alpha[j + 1] * xb[r1];
            c1 += s_alpha[256 + j + 1] * xb[r1 + 256];
            a2 += s_alpha[j + 2] * xb[r2];
            c2 += s_alpha[256 + j + 2] * xb[r2 + 256];
            a3 += s_alpha[j + 3] * xb[r3];
            c3 += s_alpha[256 + j + 3] * xb[r3 + 256];
        }
        for (; j < deg; j++) {
            size_t r0 = (size_t)s_row[j] * 512;
            a0 += s_alpha[j] * xb[r0];
            c0 += s_alpha[256 + j] * xb[r0 + 256];
        }
        s_out[tid] = fmaxf(((a0 + a1) + (a2 + a3)) * inv0 + bias[tid], 0.f);
        s_out[256 + tid] = fmaxf(((c0 + c1) + (c2 + c3)) * inv1 + bias[256 + tid], 0.f);
    } else if (deg <= 256) {
        int srow = 0;
        if (tid < deg) {
            srow = src[sorted[beg + tid]];
            s_row[tid] = srow;
        }
        for (int h = 0; h < H; h++) {
            float aldd = ald[d * H + h];
            float lg = -1e30f;
            if (tid < deg) {
                float v = als[srow * H + h] + aldd;
                lg = v > 0.f ? v : 0.2f * v;
            }
            float mx = lg;
#pragma unroll
            for (int o = 16; o > 0; o >>= 1)
                mx = fmaxf(mx, __shfl_down_sync(0xffffffffu, mx, o));
            if ((tid & 31) == 0) sh[tid >> 5] = mx;
            __syncthreads();
            if (tid < 8) {
                mx = sh[tid];
#pragma unroll
                for (int o = 4; o > 0; o >>= 1)
                    mx = fmaxf(mx, __shfl_down_sync(0xffu, mx, o));
                if (tid == 0) s_b[0] = mx;
            }
            __syncthreads();
            float gmax = s_b[0];

            float ee = (tid < deg) ? __expf(lg - gmax) : 0.f;
            s_alpha[tid] = ee;
            float sm = ee;
#pragma unroll
            for (int o = 16; o > 0; o >>= 1) sm += __shfl_down_sync(0xffffffffu, sm, o);
            if ((tid & 31) == 0) sh[tid >> 5] = sm;
            __syncthreads();
            if (tid < 8) {
                sm = sh[tid];
#pragma unroll
                for (int o = 4; o > 0; o >>= 1) sm += __shfl_down_sync(0xffu, sm, o);
                if (tid == 0) s_b[0] = sm;
            }
            __syncthreads();
            float inv = 1.f / (s_b[0] + 1e-16f);

            const float* xph = xp + h * CDIM + tid;
            float a0 = 0.f, a1 = 0.f, a2 = 0.f, a3 = 0.f;
            int j = 0;
            for (; j + 4 <= deg; j += 4) {
                a0 += s_alpha[j + 0] * xph[(size_t)s_row[j + 0] * HC];
                a1 += s_alpha[j + 1] * xph[(size_t)s_row[j + 1] * HC];
                a2 += s_alpha[j + 2] * xph[(size_t)s_row[j + 2] * HC];
                a3 += s_alpha[j + 3] * xph[(size_t)s_row[j + 3] * HC];
            }
            for (; j < deg; j++)
                a0 += s_alpha[j] * xph[(size_t)s_row[j] * HC];
            s_out[h * CDIM + tid] =
                fmaxf(((a0 + a1) + (a2 + a3)) * inv + bias[h * CDIM + tid], 0.f);
            __syncthreads();
        }
    } else {
        for (int h = 0; h < H; h++) {
            float aldd = ald[d * H + h];
            float mx = -1e30f;
            for (int i = tid; i < deg; i += 256) {
                int s = src[sorted[beg + i]];
                float v = als[s * H + h] + aldd;
                v = v > 0.f ? v : 0.2f * v;
                mx = fmaxf(mx, v);
            }
#pragma unroll
            for (int o = 16; o > 0; o >>= 1)
                mx = fmaxf(mx, __shfl_down_sync(0xffffffffu, mx, o));
            if ((tid & 31) == 0) sh[tid >> 5] = mx;
            __syncthreads();
            if (tid < 8) {
                mx = sh[tid];
#pragma unroll
                for (int o = 4; o > 0; o >>= 1)
                    mx = fmaxf(mx, __shfl_down_sync(0xffu, mx, o));
                if (tid == 0) s_b[0] = mx;
            }
            __syncthreads();
            float gmax = s_b[0];

            float sm = 0.f;
            for (int i = tid; i < deg; i += 256) {
                int s = src[sorted[beg + i]];
                float v = als[s * H + h] + aldd;
                v = v > 0.f ? v : 0.2f * v;
                sm += __expf(v - gmax);
            }
#pragma unroll
            for (int o = 16; o > 0; o >>= 1) sm += __shfl_down_sync(0xffffffffu, sm, o);
            if ((tid & 31) == 0) sh[tid >> 5] = sm;
            __syncthreads();
            if (tid < 8) {
                sm = sh[tid];
#pragma unroll
                for (int o = 4; o > 0; o >>= 1) sm += __shfl_down_sync(0xffu, sm, o);
                if (tid == 0) s_b[0] = sm;
            }
            __syncthreads();
            float inv = 1.f / (s_b[0] + 1e-16f);

            float acc = 0.f;
            for (int base = 0; base < deg; base += 256) {
                __syncthreads();
                int i = base + tid;
                if (i < deg) {
                    int s = src[sorted[beg + i]];
                    float v = als[s * H + h] + aldd;
                    v = v > 0.f ? v : 0.2f * v;
                    s_alpha[tid] = __expf(v - gmax) * inv;
                    s_row[tid]   = s;
                }
                __syncthreads();
                int lim = deg - base; if (lim > 256) lim = 256;
                for (int j = 0; j < lim; j++) {
                    acc += s_alpha[j] * xp[(size_t)s_row[j] * HC + h * CDIM + tid];
                }
            }
            s_out[h * CDIM + tid] = fmaxf(acc + bias[h * CDIM + tid], 0.f);
            __syncthreads();
        }
    }

    __syncthreads();
    int HC4 = HC >> 2;
    if (tid < HC4) {
        int c16 = tid >> 2, kq = tid & 3;
        int k0 = c16 * 16 + kq * 2;
        uint4 v;
        split_pair(s_out[k0], s_out[k0 + 1], v.x, v.z);
        split_pair(s_out[k0 + 8], s_out[k0 + 9], v.y, v.w);
        int t = d >> 7, dloc = d & 127;
        outP[((size_t)t * (HC >> 4) + c16) * 512 + kq * 128 + (dloc ^ (kq << 1))] = v;
    }
}

// --------------------------------- host -------------------------------------
static void run_gemm_f(cudaStream_t st, const uint4* Ap, const uint4* Bp,
                       const float* bias, float* C,
                       int M, int N, int K, bool relu) {
    dim3 grid((N + 127) / 128, (M + 127) / 128);
    mma_gemm_kernel<false><<<grid, 256, GEMM_SMEM, st>>>(
        M, N, K, Ap, Bp, bias, C, nullptr, 0, relu ? 1 : 0);
}

static void run_gemm_p(cudaStream_t st, const uint4* Ap, const uint4* Bp,
                       const float* bias, uint4* Cpack, int KCpackTot,
                       int M, int N, int K, bool relu) {
    dim3 grid((N + 127) / 128, (M + 127) / 128);
    mma_gemm_kernel<true><<<grid, 256, GEMM_SMEM, st>>>(
        M, N, K, Ap, Bp, bias, nullptr, Cpack, KCpackTot, relu ? 1 : 0);
}

static void run_pack_w(cudaStream_t st, const float* W, int K, int N, uint4* out) {
    int total = ((N + 127) / 128) * (K >> 4) * 512;
    pack_w_kernel<<<(total + 255) / 256, 256, 0, st>>>(W, K, N, out, total);
}

struct Tower {
    float *bufA;
    uint4 *xsP, *aggBP, *aggCP, *m1P, *m2P, *finP;
    float *als, *ald;
    int *deg, *off, *cur, *sorted;
    uint4 *pW1, *pW2, *pL1, *pL2, *pL3;
};

static void run_tower(cudaStream_t st, cudaStream_t stS,
                      cudaEvent_t evW1, cudaEvent_t evSort, cudaEvent_t evPk,
                      const Tower& T,
                      const float* x, int N, int E, const int* src, const int* dst,
                      const float* W1, const float* a1s, const float* a1d, const float* b1,
                      const float* W2, const float* a2s, const float* a2d, const float* b2,
                      const float* lw1, const float* lb1, const float* lw2, const float* lb2,
                      const float* lw3, const float* lb3) {
    int NT = (N + 127) / 128;
    int xTotal = NT * 16 * 512;
    int alGrid = (N * 32 + 255) / 256;

    run_pack_w(stS, W1, 256, 512, T.pW1);
    cudaEventRecord(evW1, stS);
    zero_int_kernel<<<(N + 256) / 256, 256, 0, stS>>>(T.deg, N + 1);
    zero_int_kernel<<<(N + 255) / 256, 256, 0, stS>>>(T.cur, N);
    hist_kernel<<<(E + 255) / 256, 256, 0, stS>>>(dst, E, T.deg);
    scan_kernel<<<1, 1024, 0, stS>>>(T.deg, T.off, N);
    scatter_kernel<<<(E + 255) / 256, 256, 0, stS>>>(dst, E, T.off, T.cur, T.sorted);
    cudaEventRecord(evSort, stS);
    run_pack_w(stS, W2, 512, 256, T.pW2);
    run_pack_w(stS, lw1, 256, 256, T.pL1);
    run_pack_w(stS, lw2, 256, 128, T.pL2);
    run_pack_w(stS, lw3, 128, 64, T.pL3);
    cudaEventRecord(evPk, stS);

    pack_x_kernel<<<(xTotal + 255) / 256, 256, 0, st>>>(x, N, 256, T.xsP, xTotal);
    cudaStreamWaitEvent(st, evW1, 0);
    run_gemm_f(st, T.xsP, T.pW1, nullptr, T.bufA, N, 512, 256, false);

    compute_al<<<alGrid, 256, 0, st>>>(T.bufA, a1s, a1d, T.als, T.ald, 2, N);
    cudaStreamWaitEvent(st, evSort, 0);
    gat_aggregate<<<N, 256, 0, st>>>(T.bufA, T.als, T.ald, src, T.sorted, T.off,
                                     b1, T.aggBP, 2);

    cudaStreamWaitEvent(st, evPk, 0);
    run_gemm_f(st, T.aggBP, T.pW2, nullptr, T.bufA, N, 256, 512, false);
    compute_al<<<alGrid, 256, 0, st>>>(T.bufA, a2s, a2d, T.als, T.ald, 1, N);
    gat_aggregate<<<N, 256, 0, st>>>(T.bufA, T.als, T.ald, src, T.sorted, T.off,
                                     b2, T.aggCP, 1);

    run_gemm_p(st, T.aggCP, T.pL1, lb1, T.m1P, 16, N, 256, 256, true);
    run_gemm_p(st, T.m1P, T.pL2, lb2, T.m2P, 8, N, 128, 256, true);
    run_gemm_p(st, T.m2P, T.pL3, lb3, T.finP, 4, N, 64, 128, true);
}

#define GSA(p, s) cudaGetSymbolAddress((void**)&(p), s)

extern "C" void kernel_launch(void* const* d_in, const int* in_sizes, int n_in,
                              void* d_out, int out_size) {
    const float* x_m  = (const float*)d_in[0];
    const float* x_d  = (const float*)d_in[1];
    const int*   eix  = (const int*)d_in[2];
    const int*   eiy  = (const int*)d_in[3];
    const float* Wx1 = (const float*)d_in[4];
    const float* ax1s = (const float*)d_in[5];
    const float* ax1d = (const float*)d_in[6];
    const float* bx1 = (const float*)d_in[7];
    const float* Wx2 = (const float*)d_in[8];
    const float* ax2s = (const float*)d_in[9];
    const float* ax2d = (const float*)d_in[10];
    const float* bx2 = (const float*)d_in[11];
    const float* Wy1 = (const float*)d_in[12];
    const float* ay1s = (const float*)d_in[13];
    const float* ay1d = (const float*)d_in[14];
    const float* by1 = (const float*)d_in[15];
    const float* Wy2 = (const float*)d_in[16];
    const float* ay2s = (const float*)d_in[17];
    const float* ay2d = (const float*)d_in[18];
    const float* by2 = (const float*)d_in[19];
    const float* lwx1 = (const float*)d_in[20];
    const float* lbx1 = (const float*)d_in[21];
    const float* lwx2 = (const float*)d_in[22];
    const float* lbx2 = (const float*)d_in[23];
    const float* lwx3 = (const float*)d_in[24];
    const float* lbx3 = (const float*)d_in[25];
    const float* lwy1 = (const float*)d_in[26];
    const float* lby1 = (const float*)d_in[27];
    const float* lwy2 = (const float*)d_in[28];
    const float* lby2 = (const float*)d_in[29];
    const float* lwy3 = (const float*)d_in[30];
    const float* lby3 = (const float*)d_in[31];

    int M  = in_sizes[0] / 256;
    int D  = in_sizes[1] / 256;
    int EX = in_sizes[2] / 2;
    int EY = in_sizes[3] / 2;

    static bool s_init = false;
    static cudaStream_t sY, sSX, sSY;
    static cudaEvent_t evRoot, evY;
    static cudaEvent_t evW1X, evSortX, evPkX, evW1Y, evSortY, evPkY;
    if (!s_init) {
        cudaStreamCreateWithFlags(&sY, cudaStreamNonBlocking);
        cudaStreamCreateWithFlags(&sSX, cudaStreamNonBlocking);
        cudaStreamCreateWithFlags(&sSY, cudaStreamNonBlocking);
        cudaEventCreateWithFlags(&evRoot, cudaEventDisableTiming);
        cudaEventCreateWithFlags(&evY, cudaEventDisableTiming);
        cudaEventCreateWithFlags(&evW1X, cudaEventDisableTiming);
        cudaEventCreateWithFlags(&evSortX, cudaEventDisableTiming);
        cudaEventCreateWithFlags(&evPkX, cudaEventDisableTiming);
        cudaEventCreateWithFlags(&evW1Y, cudaEventDisableTiming);
        cudaEventCreateWithFlags(&evSortY, cudaEventDisableTiming);
        cudaEventCreateWithFlags(&evPkY, cudaEventDisableTiming);
        cudaFuncSetAttribute(mma_gemm_kernel<false>,
                             cudaFuncAttributeMaxDynamicSharedMemorySize, GEMM_SMEM);
        cudaFuncSetAttribute(mma_gemm_kernel<true>,
                             cudaFuncAttributeMaxDynamicSharedMemorySize, GEMM_SMEM);
        cudaFuncSetAttribute(mma_gemm_final,
                             cudaFuncAttributeMaxDynamicSharedMemorySize, FGEMM_SMEM);
        s_init = true;
    }

    Tower TX, TY;
    GSA(TX.bufA, g_bufA);
    GSA(TX.xsP, g_xsP); GSA(TX.aggBP, g_aggBP);
    GSA(TX.aggCP, g_aggCP); GSA(TX.m1P, g_m1P); GSA(TX.m2P, g_m2P);
    GSA(TX.finP, g_finP);
    GSA(TX.als, g_als); GSA(TX.ald, g_ald);
    GSA(TX.deg, g_deg); GSA(TX.off, g_off); GSA(TX.cur, g_cur);
    GSA(TX.sorted, g_sorted);
    GSA(TX.pW1, g_pW1); GSA(TX.pW2, g_pW2);
    GSA(TX.pL1, g_pL1); GSA(TX.pL2, g_pL2); GSA(TX.pL3, g_pL3);

    GSA(TY.bufA, g2_bufA);
    GSA(TY.xsP, g2_xsP); GSA(TY.aggBP, g2_aggBP);
    GSA(TY.aggCP, g2_aggCP); GSA(TY.m1P, g2_m1P); GSA(TY.m2P, g2_m2P);
    GSA(TY.finP, g2_finP);
    GSA(TY.als, g2_als); GSA(TY.ald, g2_ald);
    GSA(TY.deg, g2_deg); GSA(TY.off, g2_off); GSA(TY.cur, g2_cur);
    GSA(TY.sorted, g2_sorted);
    GSA(TY.pW1, g2_pW1); GSA(TY.pW2, g2_pW2);
    GSA(TY.pL1, g2_pL1); GSA(TY.pL2, g2_pL2); GSA(TY.pL3, g2_pL3);

    cudaEventRecord(evRoot, 0);
    cudaStreamWaitEvent(sY, evRoot, 0);
    cudaStreamWaitEvent(sSX, evRoot, 0);
    cudaStreamWaitEvent(sSY, evRoot, 0);

    run_tower(0, sSX, evW1X, evSortX, evPkX, TX, x_m, M, EX, eix, eix + EX,
              Wx1, ax1s, ax1d, bx1, Wx2, ax2s, ax2d, bx2,
              lwx1, lbx1, lwx2, lbx2, lwx3, lbx3);
    run_tower(sY, sSY, evW1Y, evSortY, evPkY, TY, x_d, D, EY, eiy, eiy + EY,
              Wy1, ay1s, ay1d, by1, Wy2, ay2s, ay2d, by2,
              lwy1, lby1, lwy2, lby2, lwy3, lby3);

    cudaEventRecord(evY, sY);
    cudaStreamWaitEvent(0, evY, 0);

    // final: specialized K=64, 2-term (safe: coherent ReLU sums), streaming stores
    dim3 gridF((D + 127) / 128, (M + 127) / 128);
    mma_gemm_final<<<gridF, 256, FGEMM_SMEM>>>(M, D, TX.finP, TY.finP,
                                               (float*)d_out);
}